// round 11
// baseline (speedup 1.0000x reference)
#include <cuda_runtime.h>
#include <cuda_bf16.h>
#include <math.h>
#include <float.h>
#include <stdint.h>

#define BQ     2048
#define MKEYS  131072
#define EDIM   256
#define KDIM   128
#define VDIM   256
#define ODIM   256
#define H1     512
#define AH     128
#define IH     512
#define CDIM   (EDIM + VDIM)   // 512
#define GX     128             // CTAs along key dim in k4
#define NT     8               // key tiles (128 keys) per CTA
#define NCAND  (GX * 2 * 3)    // 768 candidates per row
#define NEG_BIG (-1e9f)

// ---------------- scratch (static device globals; no allocation) ----------------
__device__ float g_qn[BQ * KDIM];                           // 1 MB
__device__ __align__(16) __nv_bfloat16 g_qhi[BQ * KDIM];    // 512 KB
__device__ __align__(16) __nv_bfloat16 g_khi[MKEYS * KDIM]; // 32 MB
__device__ float g_invn[MKEYS];                             // 0.5 MB
__device__ float g_p3val[BQ * NCAND];                       // 6.3 MB
__device__ int   g_p3idx[BQ * NCAND];                       // 6.3 MB
__device__ float g_sterm[BQ * AH];                          // 1 MB
__device__ float g_retr[BQ * 3 * VDIM];                     // 6 MB
__device__ int   g_hit3[BQ * 3];
__device__ int   g_anyhit[BQ];
__device__ float g_comb[BQ * CDIM];                         // 4 MB
__device__ float g_g1[BQ * IH];                             // 4 MB

// ================= helpers =================
typedef unsigned long long ull;
__device__ __forceinline__ ull pack2(float x, float y) {
    ull r; asm("mov.b64 %0, {%1, %2};" : "=l"(r) : "f"(x), "f"(y)); return r;
}
__device__ __forceinline__ void fma2(ull& d, ull a, ull b) {
    asm("fma.rn.f32x2 %0, %1, %2, %0;" : "+l"(d) : "l"(a), "l"(b));
}
__device__ __forceinline__ float2 unpack2(ull v) {
    float2 f; asm("mov.b64 {%0, %1}, %2;" : "=f"(f.x), "=f"(f.y) : "l"(v)); return f;
}
__device__ __forceinline__ ull lds64(const float* p) { return *(const ull*)p; }
__device__ __forceinline__ uint32_t smem_u32(const void* p) {
    uint32_t a;
    asm("{ .reg .u64 t; cvta.to.shared.u64 t, %1; cvt.u32.u64 %0, t; }" : "=r"(a) : "l"(p));
    return a;
}
__device__ __forceinline__ void ldsm4(uint32_t* r, uint32_t addr) {
    asm volatile("ldmatrix.sync.aligned.m8n8.x4.shared.b16 {%0,%1,%2,%3}, [%4];"
                 : "=r"(r[0]), "=r"(r[1]), "=r"(r[2]), "=r"(r[3]) : "r"(addr));
}
__device__ __forceinline__ void mma16816(float* d, const uint32_t* a, const uint32_t* b) {
    asm volatile(
        "mma.sync.aligned.m16n8k16.row.col.f32.bf16.bf16.f32 "
        "{%0,%1,%2,%3}, {%4,%5,%6,%7}, {%8,%9}, {%0,%1,%2,%3};"
        : "+f"(d[0]), "+f"(d[1]), "+f"(d[2]), "+f"(d[3])
        : "r"(a[0]), "r"(a[1]), "r"(a[2]), "r"(a[3]), "r"(b[0]), "r"(b[1]));
}
__device__ __forceinline__ void cp16(uint32_t saddr, const void* gaddr) {
    asm volatile("cp.async.cg.shared.global [%0], [%1], 16;" :: "r"(saddr), "l"(gaddr));
}
#define CP_COMMIT() asm volatile("cp.async.commit_group;" ::: "memory")
#define CP_WAIT0()  asm volatile("cp.async.wait_group 0;" ::: "memory")

__device__ __forceinline__ void ins3(float& v0, float& v1, float& v2, float p) {
    float t1 = fminf(v0, p); v0 = fmaxf(v0, p);
    float t2 = fminf(v1, t1); v1 = fmaxf(v1, t1);
    v2 = fmaxf(v2, t2);
}
__device__ __forceinline__ bool better(float v, int i, float V, int I) {
    return (v > V) || (v == V && (unsigned)i < (unsigned)I);
}

// ---------------- KC: key inverse norms + normalized bf16 keys ----------------
__global__ void kc_keys(const float* __restrict__ keys) {
    int row = blockIdx.x * 8 + (threadIdx.x >> 5);
    int lane = threadIdx.x & 31;
    float4 v = ((const float4*)keys)[(size_t)row * 32 + lane];
    float s = v.x * v.x + v.y * v.y + v.z * v.z + v.w * v.w;
#pragma unroll
    for (int o = 16; o > 0; o >>= 1) s += __shfl_xor_sync(0xffffffffu, s, o);
    float in = 1.f / fmaxf(sqrtf(s), 1e-8f);
    if (lane == 0) g_invn[row] = in;
    unsigned short hb[4];
    hb[0] = __bfloat16_as_ushort(__float2bfloat16(v.x * in));
    hb[1] = __bfloat16_as_ushort(__float2bfloat16(v.y * in));
    hb[2] = __bfloat16_as_ushort(__float2bfloat16(v.z * in));
    hb[3] = __bfloat16_as_ushort(__float2bfloat16(v.w * in));
    uint2 uh;
    uh.x = (uint32_t)hb[0] | ((uint32_t)hb[1] << 16);
    uh.y = (uint32_t)hb[2] | ((uint32_t)hb[3] << 16);
    ((uint2*)g_khi)[(size_t)row * 32 + lane] = uh;
}

// ---------------- K12: fused key-encoder MLP + normalize + sterm (4 rows/CTA) ----------------
__global__ void __launch_bounds__(256) k12(const float* __restrict__ S,
                                           const float* __restrict__ kw1, const float* __restrict__ kb1,
                                           const float* __restrict__ kw2, const float* __restrict__ kb2,
                                           const float* __restrict__ aw1, const float* __restrict__ ab1) {
    __shared__ float sx[EDIM * 6];        // S transposed [c][r], 6 KB
    __shared__ float sh[H1 * 6];          // hidden transposed, 12 KB
    __shared__ float part[2][4][128];     // split-K partials, 4 KB
    __shared__ float qs[4][128];
    __shared__ float sinv[4];
    const int r0 = blockIdx.x * 4;
    const int tid = threadIdx.x;
    const int j128 = tid & 127, half = tid >> 7;

    for (int i = tid; i < 4 * EDIM; i += 256) {
        int r = i >> 8, c = i & 255;
        sx[c * 6 + r] = S[(size_t)(r0 + r) * EDIM + c];
    }
    __syncthreads();

    // phase 1: hidden = relu(S @ kw1 + kb1) -> sh (each thread 2 output cols)
#pragma unroll 1
    for (int jj = 0; jj < 2; jj++) {
        int j = jj * 256 + tid;
        float bj = kb1[j];
        ull acc[2];
        acc[0] = pack2(bj, bj); acc[1] = acc[0];
        for (int k = 0; k < EDIM; k += 8) {
            float w[8];
#pragma unroll
            for (int u = 0; u < 8; u++) w[u] = kw1[(k + u) * H1 + j];
#pragma unroll
            for (int u = 0; u < 8; u++) {
                ull wp = pack2(w[u], w[u]);
                fma2(acc[0], lds64(sx + (k + u) * 6 + 0), wp);
                fma2(acc[1], lds64(sx + (k + u) * 6 + 2), wp);
            }
        }
#pragma unroll
        for (int p = 0; p < 2; p++) {
            float2 f = unpack2(acc[p]);
            sh[j * 6 + 2 * p]     = fmaxf(f.x, 0.f);
            sh[j * 6 + 2 * p + 1] = fmaxf(f.y, 0.f);
        }
    }

    // phase S: sterm partials = S @ aw1_top (split-K over 256)
    {
        ull acc[2] = { 0ull, 0ull };
        int kbeg = half * 128;
        for (int k = kbeg; k < kbeg + 128; k += 8) {
            float w[8];
#pragma unroll
            for (int u = 0; u < 8; u++) w[u] = aw1[(k + u) * AH + j128];
#pragma unroll
            for (int u = 0; u < 8; u++) {
                ull wp = pack2(w[u], w[u]);
                fma2(acc[0], lds64(sx + (k + u) * 6 + 0), wp);
                fma2(acc[1], lds64(sx + (k + u) * 6 + 2), wp);
            }
        }
#pragma unroll
        for (int p = 0; p < 2; p++) {
            float2 f = unpack2(acc[p]);
            part[half][2 * p][j128]     = f.x;
            part[half][2 * p + 1][j128] = f.y;
        }
    }
    __syncthreads();
    if (tid < 128) {
        float bj = ab1[tid];
#pragma unroll
        for (int r = 0; r < 4; r++)
            g_sterm[(size_t)(r0 + r) * AH + tid] = part[0][r][tid] + part[1][r][tid] + bj;
    }
    __syncthreads();

    // phase 2: query = hidden @ kw2 (split-K over 512)
    {
        ull acc[2] = { 0ull, 0ull };
        int kbeg = half * 256;
        for (int k = kbeg; k < kbeg + 256; k += 8) {
            float w[8];
#pragma unroll
            for (int u = 0; u < 8; u++) w[u] = kw2[(k + u) * KDIM + j128];
#pragma unroll
            for (int u = 0; u < 8; u++) {
                ull wp = pack2(w[u], w[u]);
                fma2(acc[0], lds64(sh + (k + u) * 6 + 0), wp);
                fma2(acc[1], lds64(sh + (k + u) * 6 + 2), wp);
            }
        }
#pragma unroll
        for (int p = 0; p < 2; p++) {
            float2 f = unpack2(acc[p]);
            part[half][2 * p][j128]     = f.x;
            part[half][2 * p + 1][j128] = f.y;
        }
    }
    __syncthreads();
    if (tid < 128) {
        float bj = kb2[tid];
#pragma unroll
        for (int r = 0; r < 4; r++)
            qs[r][tid] = part[0][r][tid] + part[1][r][tid] + bj;
    }
    __syncthreads();
    {
        int wid = tid >> 5, lane = tid & 31;
        if (wid < 4) {
            float a0 = qs[wid][lane],      a1 = qs[wid][lane + 32];
            float a2 = qs[wid][lane + 64], a3 = qs[wid][lane + 96];
            float s = a0 * a0 + a1 * a1 + a2 * a2 + a3 * a3;
#pragma unroll
            for (int off = 16; off; off >>= 1) s += __shfl_xor_sync(0xffffffffu, s, off);
            if (lane == 0) sinv[wid] = 1.f / fmaxf(sqrtf(s), 1e-8f);
        }
    }
    __syncthreads();
    for (int i = tid; i < 4 * KDIM; i += 256) {
        int r = i >> 7, c = i & 127;
        float x = qs[r][c] * sinv[r];
        g_qn[(size_t)(r0 + r) * KDIM + c] = x;
        g_qhi[(size_t)(r0 + r) * KDIM + c] = __float2bfloat16(x);
    }
}

// ---------------- K4: bf16 HMMA GEMM, 4 warps x 64Mx64N tiles + running top-3 ----------------
#define AROW   136
#define TILEB  (128 * AROW * 2)     // 34816
#define SMEM_K4 (3 * TILEB)         // 104448

__device__ __forceinline__ void load_tile_cp128(uint32_t sdst, const __nv_bfloat16* __restrict__ g,
                                                int grow0, int tid) {
#pragma unroll
    for (int i = 0; i < 16; i++) {
        int idx = i * 128 + tid;
        int r = idx >> 4, c = idx & 15;
        cp16(sdst + r * (AROW * 2) + c * 16, (const void*)(g + (size_t)(grow0 + r) * KDIM + c * 8));
    }
}

__global__ void __launch_bounds__(128) k4_gemm() {
    extern __shared__ char smem[];
    const uint32_t sb = smem_u32(smem);
    const uint32_t sA = sb, sB0 = sb + TILEB, sB1 = sb + 2 * TILEB;
    const int tid = threadIdx.x;
    const int lane = tid & 31, w = tid >> 5;
    const int wm = w & 1, wn = w >> 1;       // warp grid 2M x 2N, warp tile 64x64
    const int row0 = blockIdx.y * 128;
    const int bx = blockIdx.x;
    const int m0 = wm * 64;
    const int n0 = wn * 64;

    uint32_t aAddr[4];
#pragma unroll
    for (int f = 0; f < 4; f++)
        aAddr[f] = sA + (uint32_t)(((m0 + f * 16 + (lane & 15)) * AROW + ((lane >> 4) & 1) * 8) * 2);
    const uint32_t bLane = (uint32_t)(((((lane & 7) + ((lane >> 4) << 3)) * AROW) + ((lane >> 3) & 1) * 8) * 2);

    load_tile_cp128(sA, g_qhi, row0, tid);
    load_tile_cp128(sB0, g_khi, bx * 128, tid);
    CP_COMMIT();
    CP_WAIT0();
    __syncthreads();

    // running top-3 for 8 rows per lane
    float tv0[8], tv1[8], tv2[8];
#pragma unroll
    for (int r = 0; r < 8; r++) { tv0[r] = -FLT_MAX; tv1[r] = -FLT_MAX; tv2[r] = -FLT_MAX; }
    const unsigned qb1 = (unsigned)((lane & 3) << 1);

    for (int i = 0; i < NT; i++) {
        const uint32_t sBuf = (i & 1) ? sB1 : sB0;
        if (i + 1 < NT) {
            load_tile_cp128((i & 1) ? sB0 : sB1, g_khi, ((i + 1) * GX + bx) * 128, tid);
        }
        CP_COMMIT();

        float acc[4][8][4];
#pragma unroll
        for (int f = 0; f < 4; f++)
#pragma unroll
            for (int j8 = 0; j8 < 8; j8++)
#pragma unroll
                for (int q = 0; q < 4; q++) acc[f][j8][q] = 0.f;

#pragma unroll
        for (int s = 0; s < 8; s++) {
            uint32_t a[4][4];
#pragma unroll
            for (int f = 0; f < 4; f++) ldsm4(a[f], aAddr[f] + s * 32);
#pragma unroll
            for (int g = 0; g < 4; g++) {
                uint32_t bf[4];
                ldsm4(bf, sBuf + bLane + (uint32_t)(((n0 + g * 16) * (AROW * 2))) + s * 32);
#pragma unroll
                for (int f = 0; f < 4; f++) {
                    mma16816(acc[f][2 * g],     a[f], bf);
                    mma16816(acc[f][2 * g + 1], a[f], bf + 2);
                }
            }
        }

        // running top-3: pack 9-bit payload (tile i: 3b, col-in-64: 6b) into mantissa
        const unsigned ibase = (unsigned)(i << 6) | qb1;
#pragma unroll
        for (int f = 0; f < 4; f++)
#pragma unroll
            for (int j8 = 0; j8 < 8; j8++)
#pragma unroll
                for (int q = 0; q < 4; q++) {
                    int ridx = f * 2 + (q >> 1);
                    unsigned pay = ibase | ((unsigned)j8 << 3) | (unsigned)(q & 1);
                    float p = __uint_as_float((__float_as_uint(acc[f][j8][q]) & 0xFFFFFE00u) | pay);
                    ins3(tv0[ridx], tv1[ridx], tv2[ridx], p);
                }

        CP_WAIT0();
        __syncthreads();
    }

    // merge across quad
#pragma unroll
    for (int off = 1; off <= 2; off <<= 1) {
#pragma unroll
        for (int r = 0; r < 8; r++) {
            float u0 = __shfl_xor_sync(0xffffffffu, tv0[r], off);
            float u1 = __shfl_xor_sync(0xffffffffu, tv1[r], off);
            float u2 = __shfl_xor_sync(0xffffffffu, tv2[r], off);
            ins3(tv0[r], tv1[r], tv2[r], u0);
            ins3(tv0[r], tv1[r], tv2[r], u1);
            ins3(tv0[r], tv1[r], tv2[r], u2);
        }
    }
    if ((lane & 3) == 0) {
        const int r_lo = lane >> 2;
#pragma unroll
        for (int r = 0; r < 8; r++) {
            int grow = row0 + m0 + (r >> 1) * 16 + r_lo + (r & 1) * 8;
            size_t base = (((size_t)grow * GX + bx) * 2 + wn) * 3;
            float vs[3] = { tv0[r], tv1[r], tv2[r] };
#pragma unroll
            for (int t = 0; t < 3; t++) {
                unsigned pay = __float_as_uint(vs[t]) & 511u;
                int idx = ((int)(pay >> 6) * GX + bx) * 128 + wn * 64 + (int)(pay & 63u);
                g_p3val[base + t] = vs[t];
                g_p3idx[base + t] = idx;
            }
        }
    }
}

// ---------------- K5SEL: warp-local top-8 -> merge -> exact rescore -> top-3 + gather ----------------
__global__ void __launch_bounds__(128) k5sel(const float* __restrict__ keys,
                                             const float* __restrict__ values) {
    int row = blockIdx.x;
    int tid = threadIdx.x;  // 128
    int lane = tid & 31, w = tid >> 5;
    __shared__ float qrow[KDIM];
    __shared__ float wcval[4][8];
    __shared__ int   wcid[4][8];
    __shared__ int   c_idx[8];
    __shared__ float c_val[8];
    __shared__ int   sel_s[3];
    __shared__ int   hit_s[3];

    qrow[tid] = g_qn[(size_t)row * KDIM + tid];

    // warp w owns candidates [w*192, w*192+192)
    float v[6]; int id[6];
#pragma unroll
    for (int t = 0; t < 6; t++) {
        int e = w * 192 + t * 32 + lane;
        v[t]  = g_p3val[(size_t)row * NCAND + e];
        id[t] = g_p3idx[(size_t)row * NCAND + e];
    }
    // warp-local top-8 (8 shfl-argmax rounds, no block syncs)
#pragma unroll 1
    for (int r = 0; r < 8; r++) {
        float lv = v[0]; int lt = 0;
#pragma unroll
        for (int t = 1; t < 6; t++) if (v[t] > lv) { lv = v[t]; lt = t; }
        int lid = id[lt];
        int lpos = lt * 32 + lane;
#pragma unroll
        for (int off = 16; off; off >>= 1) {
            float ov = __shfl_xor_sync(0xffffffffu, lv, off);
            int   oi = __shfl_xor_sync(0xffffffffu, lid, off);
            int   op = __shfl_xor_sync(0xffffffffu, lpos, off);
            if (ov > lv || (ov == lv && op < lpos)) { lv = ov; lid = oi; lpos = op; }
        }
        if ((lpos & 31) == lane) v[lpos >> 5] = -FLT_MAX;   // winner lane invalidates
        if (lane == 0) { wcval[w][r] = lv; wcid[w][r] = lid; }
    }
    __syncthreads();

    // warp 0 merges 4x8 -> global top-8
    if (w == 0) {
        float mv = wcval[lane >> 3][lane & 7];
        int   mi = wcid[lane >> 3][lane & 7];
#pragma unroll 1
        for (int r = 0; r < 8; r++) {
            float bv = mv; int bi = mi; int bp = lane;
#pragma unroll
            for (int off = 16; off; off >>= 1) {
                float ov = __shfl_xor_sync(0xffffffffu, bv, off);
                int   oi = __shfl_xor_sync(0xffffffffu, bi, off);
                int   op = __shfl_xor_sync(0xffffffffu, bp, off);
                if (ov > bv || (ov == bv && op < bp)) { bv = ov; bi = oi; bp = op; }
            }
            if (lane == bp) mv = -FLT_MAX;
            if (lane == 0) c_idx[r] = bi;
        }
    }
    __syncthreads();

    // exact fp32 rescore of 8 candidates
    {
        int c = tid >> 4, l = tid & 15;
        int idx = c_idx[c];
        float part = 0.f;
#pragma unroll
        for (int jj = 0; jj < 8; jj++) {
            int k = l + jj * 16;
            part += qrow[k] * keys[(size_t)idx * KDIM + k];
        }
#pragma unroll
        for (int off = 8; off; off >>= 1) part += __shfl_xor_sync(0xffffffffu, part, off);
        if (l == 0) c_val[c] = part * g_invn[idx];
    }
    __syncthreads();

    if (tid == 0) {
        int used = 0;
#pragma unroll
        for (int k = 0; k < 3; k++) {
            float bv = -FLT_MAX; int bi = 0x7fffffff; int bs = -1;
#pragma unroll
            for (int t = 0; t < 8; t++) {
                if (used & (1 << t)) continue;
                if (better(c_val[t], c_idx[t], bv, bi)) { bv = c_val[t]; bi = c_idx[t]; bs = t; }
            }
            used |= (1 << bs);
            sel_s[k] = bi; hit_s[k] = (bv >= 0.0f);
        }
        g_anyhit[row] = hit_s[0] | hit_s[1] | hit_s[2];
        g_hit3[row * 3 + 0] = hit_s[0];
        g_hit3[row * 3 + 1] = hit_s[1];
        g_hit3[row * 3 + 2] = hit_s[2];
    }
    __syncthreads();

#pragma unroll
    for (int t = 0; t < 3; t++) {
        int idx = sel_s[t];
        for (int d = tid; d < VDIM; d += 128)
            g_retr[((size_t)row * 3 + t) * VDIM + d] = values[(size_t)idx * VDIM + d];
    }
}

// ---------------- K6M: attention + softmax + mem_vec -> g_comb (4 rows/CTA) ----------------
#define K6M_SMEM ((12 * 256 + 12 * 132) * 4)   // 18624 B
__global__ void __launch_bounds__(256) k6m(const float* __restrict__ S,
                                           const float* __restrict__ aw1,
                                           const float* __restrict__ aw2,
                                           const float* __restrict__ ab2) {
    extern __shared__ char dsm[];
    float* retr = (float*)dsm;          // [12][256]
    float* red  = retr + 12 * 256;      // [12][132]
    __shared__ float sterm_s[4 * 128];
    __shared__ float lgs[12];
    __shared__ float attn_s[4][3];

    const int row0 = blockIdx.x * 4;
    const int tid = threadIdx.x;

    for (int idx = tid; idx < 12 * VDIM; idx += 256)
        retr[idx] = g_retr[(size_t)row0 * 3 * VDIM + idx];
    for (int idx = tid; idx < 4 * AH; idx += 256)
        sterm_s[idx] = g_sterm[(size_t)row0 * AH + idx];
    __syncthreads();

    {
        int j = tid & 127, grp = tid >> 7;  // grp handles 6 triples
        float acc[6];
#pragma unroll
        for (int rt = 0; rt < 6; rt++) acc[rt] = sterm_s[((grp * 6 + rt) / 3) * 128 + j];
        for (int k = 0; k < VDIM; k += 2) {
            float w0 = aw1[(EDIM + k) * AH + j];
            float w1 = aw1[(EDIM + k + 1) * AH + j];
#pragma unroll
            for (int rt = 0; rt < 6; rt++) {
                int g = grp * 6 + rt;
                acc[rt] = fmaf(retr[g * 256 + k],     w0, acc[rt]);
                acc[rt] = fmaf(retr[g * 256 + k + 1], w1, acc[rt]);
            }
        }
        float w2 = aw2[j];
#pragma unroll
        for (int rt = 0; rt < 6; rt++)
            red[(grp * 6 + rt) * 132 + j] = tanhf(acc[rt]) * w2;
    }
    __syncthreads();

    {
        int wid = tid >> 5, lane = tid & 31;
        float b2 = ab2[0];
#pragma unroll
        for (int u = 0; u < 2; u++) {
            int rt = wid * 2 + u;
            if (rt < 12) {
                float s = red[rt * 132 + lane] + red[rt * 132 + lane + 32]
                        + red[rt * 132 + lane + 64] + red[rt * 132 + lane + 96];
#pragma unroll
                for (int off = 16; off; off >>= 1) s += __shfl_xor_sync(0xffffffffu, s, off);
                if (lane == 0)
                    lgs[rt] = g_hit3[(size_t)row0 * 3 + rt] ? (s + b2) : NEG_BIG;
            }
        }
    }
    __syncthreads();
    if (tid < 4) {
        float l0 = lgs[tid * 3 + 0], l1 = lgs[tid * 3 + 1], l2 = lgs[tid * 3 + 2];
        float m = fmaxf(l0, fmaxf(l1, l2));
        float e0 = expf(l0 - m), e1 = expf(l1 - m), e2 = expf(l2 - m);
        float inv = 1.f / (e0 + e1 + e2);
        attn_s[tid][0] = e0 * inv; attn_s[tid][1] = e1 * inv; attn_s[tid][2] = e2 * inv;
    }
    __syncthreads();

    for (int idx = tid; idx < 4 * CDIM; idx += 256) {
        int r = idx >> 9, c = idx & 511;
        float val;
        if (c < EDIM) {
            val = S[(size_t)(row0 + r) * EDIM + c];
        } else {
            int d = c - EDIM;
            val = attn_s[r][0] * retr[(r * 3 + 0) * 256 + d]
                + attn_s[r][1] * retr[(r * 3 + 1) * 256 + d]
                + attn_s[r][2] * retr[(r * 3 + 2) * 256 + d];
        }
        g_comb[(size_t)(row0 + r) * CDIM + c] = val;
    }
}

// ---------------- K7: g1 = relu(comb @ i_w1 + i_b1)  (8 rows/CTA) ----------------
__global__ void __launch_bounds__(256) k7_int1(const float* __restrict__ W,
                                               const float* __restrict__ b) {
    __shared__ float xs[CDIM * 10];   // 20 KB
    int r0 = blockIdx.x * 8;
    int tid = threadIdx.x;
    int j = blockIdx.y * 256 + tid;
    for (int i = tid; i < 8 * CDIM; i += 256) {
        int r = i >> 9, c = i & 511;
        xs[c * 10 + r] = g_comb[(size_t)(r0 + r) * CDIM + c];
    }
    __syncthreads();
    float bj = b[j];
    ull acc[4];
#pragma unroll
    for (int p = 0; p < 4; p++) acc[p] = pack2(bj, bj);
    for (int k = 0; k < CDIM; k += 8) {
        float w[8];
#pragma unroll
        for (int u = 0; u < 8; u++) w[u] = W[(k + u) * IH + j];
#pragma unroll
        for (int u = 0; u < 8; u++) {
            ull wp = pack2(w[u], w[u]);
#pragma unroll
            for (int p = 0; p < 4; p++)
                fma2(acc[p], lds64(xs + (k + u) * 10 + 2 * p), wp);
        }
    }
#pragma unroll
    for (int p = 0; p < 4; p++) {
        float2 f = unpack2(acc[p]);
        g_g1[(size_t)(r0 + 2 * p) * IH + j]     = fmaxf(f.x, 0.f);
        g_g1[(size_t)(r0 + 2 * p + 1) * IH + j] = fmaxf(f.y, 0.f);
    }
}

// ---------------- K8: out = g1 @ i_w2 + i_b2  (4 rows/CTA) ----------------
__global__ void __launch_bounds__(256) k8_int2(const float* __restrict__ W,
                                               const float* __restrict__ b,
                                               float* __restrict__ out) {
    __shared__ float xs[IH * 6];   // 12 KB
    int r0 = blockIdx.x * 4;
    int tid = threadIdx.x;          // j = tid, ODIM == 256
    for (int i = tid; i < 4 * IH; i += 256) {
        int r = i >> 9, c = i & 511;
        xs[c * 6 + r] = g_g1[(size_t)(r0 + r) * IH + c];
    }
    __syncthreads();
    float bj = b[tid];
    ull acc[2];
#pragma unroll
    for (int p = 0; p < 2; p++) acc[p] = pack2(bj, bj);
    for (int k = 0; k < IH; k += 8) {
        float w[8];
#pragma unroll
        for (int u = 0; u < 8; u++) w[u] = W[(k + u) * ODIM + tid];
#pragma unroll
        for (int u = 0; u < 8; u++) {
            ull wp = pack2(w[u], w[u]);
#pragma unroll
            for (int p = 0; p < 2; p++)
                fma2(acc[p], lds64(xs + (k + u) * 6 + 2 * p), wp);
        }
    }
#pragma unroll
    for (int p = 0; p < 2; p++) {
        float2 f = unpack2(acc[p]);
        out[(size_t)(r0 + 2 * p) * ODIM + tid]     = f.x;
        out[(size_t)(r0 + 2 * p + 1) * ODIM + tid] = f.y;
    }
}

// ---------------- K9: fallback path for rows with no hit (rare/never) ----------------
__global__ void k9_fallback(const float* __restrict__ S,
                            const float* __restrict__ fw1, const float* __restrict__ fb1,
                            const float* __restrict__ fw2, const float* __restrict__ fb2,
                            float* __restrict__ out) {
    int row = blockIdx.x;
    if (g_anyhit[row]) return;
    __shared__ float xs[EDIM];
    __shared__ float h[IH];
    int tid = threadIdx.x;  // 256
    for (int i = tid; i < EDIM; i += 256) xs[i] = S[(size_t)row * EDIM + i];
    __syncthreads();
    for (int j = tid; j < IH; j += 256) {
        float a = fb1[j];
        for (int k = 0; k < EDIM; k++) a = fmaf(xs[k], fw1[k * IH + j], a);
        h[j] = fmaxf(a, 0.f);
    }
    __syncthreads();
    {
        int j = tid;
        float a = fb2[j];
        for (int k = 0; k < IH; k++) a = fmaf(h[k], fw2[k * ODIM + j], a);
        out[(size_t)row * ODIM + j] = a;
    }
}

// ---------------- launch ----------------
extern "C" void kernel_launch(void* const* d_in, const int* in_sizes, int n_in,
                              void* d_out, int out_size) {
    const float* S    = (const float*)d_in[0];
    const float* keys = (const float*)d_in[1];
    const float* vals = (const float*)d_in[2];
    const float* kw1  = (const float*)d_in[3];
    const float* kb1  = (const float*)d_in[4];
    const float* kw2  = (const float*)d_in[5];
    const float* kb2  = (const float*)d_in[6];
    const float* aw1  = (const float*)d_in[7];
    const float* ab1  = (const float*)d_in[8];
    const float* aw2  = (const float*)d_in[9];
    const float* ab2  = (const float*)d_in[10];
    const float* iw1  = (const float*)d_in[11];
    const float* ib1  = (const float*)d_in[12];
    const float* iw2  = (const float*)d_in[13];
    const float* ib2  = (const float*)d_in[14];
    const float* fw1  = (const float*)d_in[15];
    const float* fb1  = (const float*)d_in[16];
    const float* fw2  = (const float*)d_in[17];
    const float* fb2  = (const float*)d_in[18];
    float* out = (float*)d_out;

    static int configured = 0;
    if (!configured) {
        cudaFuncSetAttribute(k4_gemm, cudaFuncAttributeMaxDynamicSharedMemorySize, SMEM_K4);
        configured = 1;
    }

    kc_keys<<<MKEYS / 8, 256>>>(keys);
    k12<<<BQ / 4, 256>>>(S, kw1, kb1, kw2, kb2, aw1, ab1);
    k4_gemm<<<dim3(GX, BQ / 128), 128, SMEM_K4>>>();
    k5sel<<<BQ, 128>>>(keys, vals);
    k6m<<<BQ / 4, 256, K6M_SMEM>>>(S, aw1, aw2, ab2);
    k7_int1<<<dim3(BQ / 8, 2), 256>>>(iw1, ib1);
    k8_int2<<<BQ / 4, 256>>>(iw2, ib2, out);
    k9_fallback<<<BQ, 256>>>(S, fw1, fb1, fw2, fb2, out);
}

// round 12
// speedup vs baseline: 1.0347x; 1.0347x over previous
#include <cuda_runtime.h>
#include <cuda_bf16.h>
#include <math.h>
#include <float.h>
#include <stdint.h>

#define BQ     2048
#define MKEYS  131072
#define EDIM   256
#define KDIM   128
#define VDIM   256
#define ODIM   256
#define H1     512
#define AH     128
#define IH     512
#define CDIM   (EDIM + VDIM)   // 512
#define GX     128             // CTAs along key dim in k4
#define NT     8               // key tiles (128 keys) per CTA
#define NCAND  (GX * 2 * 3)    // 768 candidates per row
#define NEG_BIG (-1e9f)

// ---------------- scratch (static device globals; no allocation) ----------------
__device__ float g_qn[BQ * KDIM];                           // 1 MB
__device__ __align__(16) __nv_bfloat16 g_qhi[BQ * KDIM];    // 512 KB
__device__ __align__(16) __nv_bfloat16 g_khi[MKEYS * KDIM]; // 32 MB
__device__ float g_invn[MKEYS];                             // 0.5 MB
__device__ float g_p3val[BQ * NCAND];                       // 6.3 MB (idx reconstructed from payload)
__device__ float g_sterm[BQ * AH];                          // 1 MB
__device__ float g_retr[BQ * 3 * VDIM];                     // 6 MB
__device__ int   g_hit3[BQ * 3];
__device__ int   g_anyhit[BQ];
__device__ float g_comb[BQ * CDIM];                         // 4 MB
__device__ float g_g1[BQ * IH];                             // 4 MB

// ================= helpers =================
typedef unsigned long long ull;
__device__ __forceinline__ ull pack2(float x, float y) {
    ull r; asm("mov.b64 %0, {%1, %2};" : "=l"(r) : "f"(x), "f"(y)); return r;
}
__device__ __forceinline__ void fma2(ull& d, ull a, ull b) {
    asm("fma.rn.f32x2 %0, %1, %2, %0;" : "+l"(d) : "l"(a), "l"(b));
}
__device__ __forceinline__ float2 unpack2(ull v) {
    float2 f; asm("mov.b64 {%0, %1}, %2;" : "=f"(f.x), "=f"(f.y) : "l"(v)); return f;
}
__device__ __forceinline__ ull lds64(const float* p) { return *(const ull*)p; }
__device__ __forceinline__ uint32_t smem_u32(const void* p) {
    uint32_t a;
    asm("{ .reg .u64 t; cvta.to.shared.u64 t, %1; cvt.u32.u64 %0, t; }" : "=r"(a) : "l"(p));
    return a;
}
__device__ __forceinline__ void ldsm4(uint32_t* r, uint32_t addr) {
    asm volatile("ldmatrix.sync.aligned.m8n8.x4.shared.b16 {%0,%1,%2,%3}, [%4];"
                 : "=r"(r[0]), "=r"(r[1]), "=r"(r[2]), "=r"(r[3]) : "r"(addr));
}
__device__ __forceinline__ void mma16816(float* d, const uint32_t* a, const uint32_t* b) {
    asm volatile(
        "mma.sync.aligned.m16n8k16.row.col.f32.bf16.bf16.f32 "
        "{%0,%1,%2,%3}, {%4,%5,%6,%7}, {%8,%9}, {%0,%1,%2,%3};"
        : "+f"(d[0]), "+f"(d[1]), "+f"(d[2]), "+f"(d[3])
        : "r"(a[0]), "r"(a[1]), "r"(a[2]), "r"(a[3]), "r"(b[0]), "r"(b[1]));
}
__device__ __forceinline__ void cp16(uint32_t saddr, const void* gaddr) {
    asm volatile("cp.async.cg.shared.global [%0], [%1], 16;" :: "r"(saddr), "l"(gaddr));
}
#define CP_COMMIT() asm volatile("cp.async.commit_group;" ::: "memory")
#define CP_WAIT0()  asm volatile("cp.async.wait_group 0;" ::: "memory")

__device__ __forceinline__ void ins3(float& v0, float& v1, float& v2, float p) {
    float t1 = fminf(v0, p); v0 = fmaxf(v0, p);
    float t2 = fminf(v1, t1); v1 = fmaxf(v1, t1);
    v2 = fmaxf(v2, t2);
}
__device__ __forceinline__ bool better(float v, int i, float V, int I) {
    return (v > V) || (v == V && (unsigned)i < (unsigned)I);
}

// ---------------- KC: key inverse norms + normalized bf16 keys ----------------
__global__ void kc_keys(const float* __restrict__ keys) {
    int row = blockIdx.x * 8 + (threadIdx.x >> 5);
    int lane = threadIdx.x & 31;
    float4 v = ((const float4*)keys)[(size_t)row * 32 + lane];
    float s = v.x * v.x + v.y * v.y + v.z * v.z + v.w * v.w;
#pragma unroll
    for (int o = 16; o > 0; o >>= 1) s += __shfl_xor_sync(0xffffffffu, s, o);
    float in = 1.f / fmaxf(sqrtf(s), 1e-8f);
    if (lane == 0) g_invn[row] = in;
    unsigned short hb[4];
    hb[0] = __bfloat16_as_ushort(__float2bfloat16(v.x * in));
    hb[1] = __bfloat16_as_ushort(__float2bfloat16(v.y * in));
    hb[2] = __bfloat16_as_ushort(__float2bfloat16(v.z * in));
    hb[3] = __bfloat16_as_ushort(__float2bfloat16(v.w * in));
    uint2 uh;
    uh.x = (uint32_t)hb[0] | ((uint32_t)hb[1] << 16);
    uh.y = (uint32_t)hb[2] | ((uint32_t)hb[3] << 16);
    ((uint2*)g_khi)[(size_t)row * 32 + lane] = uh;
}

// ---------------- K12: fused key-encoder MLP + normalize + sterm (4 rows/CTA) ----------------
__global__ void __launch_bounds__(256) k12(const float* __restrict__ S,
                                           const float* __restrict__ kw1, const float* __restrict__ kb1,
                                           const float* __restrict__ kw2, const float* __restrict__ kb2,
                                           const float* __restrict__ aw1, const float* __restrict__ ab1) {
    __shared__ float sx[EDIM * 6];        // S transposed [c][r], 6 KB
    __shared__ float sh[H1 * 6];          // hidden transposed, 12 KB
    __shared__ float part[2][4][128];     // split-K partials, 4 KB
    __shared__ float qs[4][128];
    __shared__ float sinv[4];
    const int r0 = blockIdx.x * 4;
    const int tid = threadIdx.x;
    const int j128 = tid & 127, half = tid >> 7;

    for (int i = tid; i < 4 * EDIM; i += 256) {
        int r = i >> 8, c = i & 255;
        sx[c * 6 + r] = S[(size_t)(r0 + r) * EDIM + c];
    }
    __syncthreads();

    // phase 1: hidden = relu(S @ kw1 + kb1) -> sh (each thread 2 output cols)
#pragma unroll 1
    for (int jj = 0; jj < 2; jj++) {
        int j = jj * 256 + tid;
        float bj = kb1[j];
        ull acc[2];
        acc[0] = pack2(bj, bj); acc[1] = acc[0];
        for (int k = 0; k < EDIM; k += 8) {
            float w[8];
#pragma unroll
            for (int u = 0; u < 8; u++) w[u] = kw1[(k + u) * H1 + j];
#pragma unroll
            for (int u = 0; u < 8; u++) {
                ull wp = pack2(w[u], w[u]);
                fma2(acc[0], lds64(sx + (k + u) * 6 + 0), wp);
                fma2(acc[1], lds64(sx + (k + u) * 6 + 2), wp);
            }
        }
#pragma unroll
        for (int p = 0; p < 2; p++) {
            float2 f = unpack2(acc[p]);
            sh[j * 6 + 2 * p]     = fmaxf(f.x, 0.f);
            sh[j * 6 + 2 * p + 1] = fmaxf(f.y, 0.f);
        }
    }

    // phase S: sterm partials = S @ aw1_top (split-K over 256)
    {
        ull acc[2] = { 0ull, 0ull };
        int kbeg = half * 128;
        for (int k = kbeg; k < kbeg + 128; k += 8) {
            float w[8];
#pragma unroll
            for (int u = 0; u < 8; u++) w[u] = aw1[(k + u) * AH + j128];
#pragma unroll
            for (int u = 0; u < 8; u++) {
                ull wp = pack2(w[u], w[u]);
                fma2(acc[0], lds64(sx + (k + u) * 6 + 0), wp);
                fma2(acc[1], lds64(sx + (k + u) * 6 + 2), wp);
            }
        }
#pragma unroll
        for (int p = 0; p < 2; p++) {
            float2 f = unpack2(acc[p]);
            part[half][2 * p][j128]     = f.x;
            part[half][2 * p + 1][j128] = f.y;
        }
    }
    __syncthreads();
    if (tid < 128) {
        float bj = ab1[tid];
#pragma unroll
        for (int r = 0; r < 4; r++)
            g_sterm[(size_t)(r0 + r) * AH + tid] = part[0][r][tid] + part[1][r][tid] + bj;
    }
    __syncthreads();

    // phase 2: query = hidden @ kw2 (split-K over 512)
    {
        ull acc[2] = { 0ull, 0ull };
        int kbeg = half * 256;
        for (int k = kbeg; k < kbeg + 256; k += 8) {
            float w[8];
#pragma unroll
            for (int u = 0; u < 8; u++) w[u] = kw2[(k + u) * KDIM + j128];
#pragma unroll
            for (int u = 0; u < 8; u++) {
                ull wp = pack2(w[u], w[u]);
                fma2(acc[0], lds64(sh + (k + u) * 6 + 0), wp);
                fma2(acc[1], lds64(sh + (k + u) * 6 + 2), wp);
            }
        }
#pragma unroll
        for (int p = 0; p < 2; p++) {
            float2 f = unpack2(acc[p]);
            part[half][2 * p][j128]     = f.x;
            part[half][2 * p + 1][j128] = f.y;
        }
    }
    __syncthreads();
    if (tid < 128) {
        float bj = kb2[tid];
#pragma unroll
        for (int r = 0; r < 4; r++)
            qs[r][tid] = part[0][r][tid] + part[1][r][tid] + bj;
    }
    __syncthreads();
    {
        int wid = tid >> 5, lane = tid & 31;
        if (wid < 4) {
            float a0 = qs[wid][lane],      a1 = qs[wid][lane + 32];
            float a2 = qs[wid][lane + 64], a3 = qs[wid][lane + 96];
            float s = a0 * a0 + a1 * a1 + a2 * a2 + a3 * a3;
#pragma unroll
            for (int off = 16; off; off >>= 1) s += __shfl_xor_sync(0xffffffffu, s, off);
            if (lane == 0) sinv[wid] = 1.f / fmaxf(sqrtf(s), 1e-8f);
        }
    }
    __syncthreads();
    for (int i = tid; i < 4 * KDIM; i += 256) {
        int r = i >> 7, c = i & 127;
        float x = qs[r][c] * sinv[r];
        g_qn[(size_t)(r0 + r) * KDIM + c] = x;
        g_qhi[(size_t)(r0 + r) * KDIM + c] = __float2bfloat16(x);
    }
}

// ---------------- K4: bf16 HMMA GEMM + running per-lane top-3 (R10-proven, val-only output) ----------------
#define AROW   136
#define TILEB  (128 * AROW * 2)     // 34816
#define SMEM_K4 (3 * TILEB)         // 104448

__device__ __forceinline__ void load_tile_cp(uint32_t sdst, const __nv_bfloat16* __restrict__ g,
                                             int grow0, int tid) {
#pragma unroll
    for (int i = 0; i < 8; i++) {
        int idx = i * 256 + tid;
        int r = idx >> 4, c = idx & 15;
        cp16(sdst + r * (AROW * 2) + c * 16, (const void*)(g + (size_t)(grow0 + r) * KDIM + c * 8));
    }
}

__global__ void __launch_bounds__(256, 2) k4_gemm() {
    extern __shared__ char smem[];
    const uint32_t sb = smem_u32(smem);
    const uint32_t sA = sb, sB0 = sb + TILEB, sB1 = sb + 2 * TILEB;
    const int tid = threadIdx.x;
    const int lane = tid & 31, w = tid >> 5;
    const int wm = w & 3, wn = w >> 2;       // warp grid 4M x 2N
    const int row0 = blockIdx.y * 128;
    const int bx = blockIdx.x;
    const int m0 = wm * 32;

    uint32_t aAddr[2];
#pragma unroll
    for (int f = 0; f < 2; f++)
        aAddr[f] = sA + (uint32_t)(((m0 + f * 16 + (lane & 15)) * AROW + ((lane >> 4) & 1) * 8) * 2);
    const uint32_t bLane = (uint32_t)(((((lane & 7) + ((lane >> 4) << 3)) * AROW) + ((lane >> 3) & 1) * 8) * 2);

    load_tile_cp(sA, g_qhi, row0, tid);
    load_tile_cp(sB0, g_khi, bx * 128, tid);
    CP_COMMIT();
    CP_WAIT0();
    __syncthreads();

    float tv0[4], tv1[4], tv2[4];
#pragma unroll
    for (int r = 0; r < 4; r++) { tv0[r] = -FLT_MAX; tv1[r] = -FLT_MAX; tv2[r] = -FLT_MAX; }
    const unsigned qb1 = (unsigned)((lane & 3) << 1);

    for (int i = 0; i < NT; i++) {
        const uint32_t sBuf = (i & 1) ? sB1 : sB0;
        if (i + 1 < NT) {
            load_tile_cp((i & 1) ? sB0 : sB1, g_khi, ((i + 1) * GX + bx) * 128, tid);
        }
        CP_COMMIT();

        float acc[2][8][4];
#pragma unroll
        for (int f = 0; f < 2; f++)
#pragma unroll
            for (int j8 = 0; j8 < 8; j8++)
#pragma unroll
                for (int q = 0; q < 4; q++) acc[f][j8][q] = 0.f;

#pragma unroll
        for (int s = 0; s < 8; s++) {
            uint32_t a0[4], a1[4];
            ldsm4(a0, aAddr[0] + s * 32);
            ldsm4(a1, aAddr[1] + s * 32);
#pragma unroll
            for (int g = 0; g < 4; g++) {
                uint32_t bf[4];
                ldsm4(bf, sBuf + bLane + (uint32_t)(((wn * 4 + g) * 16) * (AROW * 2)) + s * 32);
                mma16816(acc[0][2 * g],     a0, bf);
                mma16816(acc[0][2 * g + 1], a0, bf + 2);
                mma16816(acc[1][2 * g],     a1, bf);
                mma16816(acc[1][2 * g + 1], a1, bf + 2);
            }
        }

        // running top-3: pack 9-bit payload (tile i: 3b, col-in-64: 6b) into mantissa
        const unsigned ibase = (unsigned)(i << 6) | qb1;
#pragma unroll
        for (int f = 0; f < 2; f++)
#pragma unroll
            for (int j8 = 0; j8 < 8; j8++)
#pragma unroll
                for (int q = 0; q < 4; q++) {
                    int ridx = f * 2 + (q >> 1);
                    unsigned pay = ibase | ((unsigned)j8 << 3) | (unsigned)(q & 1);
                    float p = __uint_as_float((__float_as_uint(acc[f][j8][q]) & 0xFFFFFE00u) | pay);
                    ins3(tv0[ridx], tv1[ridx], tv2[ridx], p);
                }

        CP_WAIT0();
        __syncthreads();
    }

    // merge across quad
#pragma unroll
    for (int off = 1; off <= 2; off <<= 1) {
#pragma unroll
        for (int r = 0; r < 4; r++) {
            float u0 = __shfl_xor_sync(0xffffffffu, tv0[r], off);
            float u1 = __shfl_xor_sync(0xffffffffu, tv1[r], off);
            float u2 = __shfl_xor_sync(0xffffffffu, tv2[r], off);
            ins3(tv0[r], tv1[r], tv2[r], u0);
            ins3(tv0[r], tv1[r], tv2[r], u1);
            ins3(tv0[r], tv1[r], tv2[r], u2);
        }
    }
    if ((lane & 3) == 0) {
        const int r_lo = lane >> 2;
#pragma unroll
        for (int r = 0; r < 4; r++) {
            int grow = row0 + m0 + (r >> 1) * 16 + r_lo + (r & 1) * 8;
            size_t base = (((size_t)grow * GX + bx) * 2 + wn) * 3;
            g_p3val[base + 0] = tv0[r];
            g_p3val[base + 1] = tv1[r];
            g_p3val[base + 2] = tv2[r];
        }
    }
}

// ---------------- K5SEL: warp-local top-8 (idx reconstructed) -> rescore -> top-3 + gather ----------------
__global__ void __launch_bounds__(128) k5sel(const float* __restrict__ keys,
                                             const float* __restrict__ values) {
    int row = blockIdx.x;
    int tid = threadIdx.x;  // 128
    int lane = tid & 31, w = tid >> 5;
    __shared__ float qrow[KDIM];
    __shared__ float wcval[4][8];
    __shared__ int   wcid[4][8];
    __shared__ int   c_idx[8];
    __shared__ float c_val[8];
    __shared__ int   sel_s[3];
    __shared__ int   hit_s[3];

    qrow[tid] = g_qn[(size_t)row * KDIM + tid];

    // warp w owns candidates [w*192, w*192+192); idx reconstructed from position + payload
    float v[6]; int id[6];
#pragma unroll
    for (int t = 0; t < 6; t++) {
        int e = w * 192 + t * 32 + lane;
        float val = g_p3val[(size_t)row * NCAND + e];
        v[t] = val;
        unsigned pay = __float_as_uint(val) & 511u;
        int bx = e / 6, wnn = (e / 3) & 1;
        id[t] = ((int)(pay >> 6) * GX + bx) * 128 + wnn * 64 + (int)(pay & 63u);
    }
    // warp-local top-8 (8 shfl-argmax rounds, no block syncs)
#pragma unroll 1
    for (int r = 0; r < 8; r++) {
        float lv = v[0]; int lt = 0;
#pragma unroll
        for (int t = 1; t < 6; t++) if (v[t] > lv) { lv = v[t]; lt = t; }
        int lid = id[lt];
        int lpos = lt * 32 + lane;
#pragma unroll
        for (int off = 16; off; off >>= 1) {
            float ov = __shfl_xor_sync(0xffffffffu, lv, off);
            int   oi = __shfl_xor_sync(0xffffffffu, lid, off);
            int   op = __shfl_xor_sync(0xffffffffu, lpos, off);
            if (ov > lv || (ov == lv && op < lpos)) { lv = ov; lid = oi; lpos = op; }
        }
        if ((lpos & 31) == lane) v[lpos >> 5] = -FLT_MAX;   // winner lane invalidates
        if (lane == 0) { wcval[w][r] = lv; wcid[w][r] = lid; }
    }
    __syncthreads();

    // warp 0 merges 4x8 -> global top-8
    if (w == 0) {
        float mv = wcval[lane >> 3][lane & 7];
        int   mi = wcid[lane >> 3][lane & 7];
#pragma unroll 1
        for (int r = 0; r < 8; r++) {
            float bv = mv; int bi = mi; int bp = lane;
#pragma unroll
            for (int off = 16; off; off >>= 1) {
                float ov = __shfl_xor_sync(0xffffffffu, bv, off);
                int   oi = __shfl_xor_sync(0xffffffffu, bi, off);
                int   op = __shfl_xor_sync(0xffffffffu, bp, off);
                if (ov > bv || (ov == bv && op < bp)) { bv = ov; bi = oi; bp = op; }
            }
            if (lane == bp) mv = -FLT_MAX;
            if (lane == 0) c_idx[r] = bi;
        }
    }
    __syncthreads();

    // exact fp32 rescore of 8 candidates
    {
        int c = tid >> 4, l = tid & 15;
        int idx = c_idx[c];
        float part = 0.f;
#pragma unroll
        for (int jj = 0; jj < 8; jj++) {
            int k = l + jj * 16;
            part += qrow[k] * keys[(size_t)idx * KDIM + k];
        }
#pragma unroll
        for (int off = 8; off; off >>= 1) part += __shfl_xor_sync(0xffffffffu, part, off);
        if (l == 0) c_val[c] = part * g_invn[idx];
    }
    __syncthreads();

    if (tid == 0) {
        int used = 0;
#pragma unroll
        for (int k = 0; k < 3; k++) {
            float bv = -FLT_MAX; int bi = 0x7fffffff; int bs = -1;
#pragma unroll
            for (int t = 0; t < 8; t++) {
                if (used & (1 << t)) continue;
                if (better(c_val[t], c_idx[t], bv, bi)) { bv = c_val[t]; bi = c_idx[t]; bs = t; }
            }
            used |= (1 << bs);
            sel_s[k] = bi; hit_s[k] = (bv >= 0.0f);
        }
        g_anyhit[row] = hit_s[0] | hit_s[1] | hit_s[2];
        g_hit3[row * 3 + 0] = hit_s[0];
        g_hit3[row * 3 + 1] = hit_s[1];
        g_hit3[row * 3 + 2] = hit_s[2];
    }
    __syncthreads();

#pragma unroll
    for (int t = 0; t < 3; t++) {
        int idx = sel_s[t];
        for (int d = tid; d < VDIM; d += 128)
            g_retr[((size_t)row * 3 + t) * VDIM + d] = values[(size_t)idx * VDIM + d];
    }
}

// ---------------- K6M: attention + softmax + mem_vec -> g_comb (4 rows/CTA) ----------------
#define K6M_SMEM ((12 * 256 + 12 * 132) * 4)   // 18624 B
__global__ void __launch_bounds__(256) k6m(const float* __restrict__ S,
                                           const float* __restrict__ aw1,
                                           const float* __restrict__ aw2,
                                           const float* __restrict__ ab2) {
    extern __shared__ char dsm[];
    float* retr = (float*)dsm;          // [12][256]
    float* red  = retr + 12 * 256;      // [12][132]
    __shared__ float sterm_s[4 * 128];
    __shared__ float lgs[12];
    __shared__ float attn_s[4][3];

    const int row0 = blockIdx.x * 4;
    const int tid = threadIdx.x;

    for (int idx = tid; idx < 12 * VDIM; idx += 256)
        retr[idx] = g_retr[(size_t)row0 * 3 * VDIM + idx];
    for (int idx = tid; idx < 4 * AH; idx += 256)
        sterm_s[idx] = g_sterm[(size_t)row0 * AH + idx];
    __syncthreads();

    {
        int j = tid & 127, grp = tid >> 7;  // grp handles 6 triples
        float acc[6];
#pragma unroll
        for (int rt = 0; rt < 6; rt++) acc[rt] = sterm_s[((grp * 6 + rt) / 3) * 128 + j];
        for (int k = 0; k < VDIM; k += 2) {
            float w0 = aw1[(EDIM + k) * AH + j];
            float w1 = aw1[(EDIM + k + 1) * AH + j];
#pragma unroll
            for (int rt = 0; rt < 6; rt++) {
                int g = grp * 6 + rt;
                acc[rt] = fmaf(retr[g * 256 + k],     w0, acc[rt]);
                acc[rt] = fmaf(retr[g * 256 + k + 1], w1, acc[rt]);
            }
        }
        float w2 = aw2[j];
#pragma unroll
        for (int rt = 0; rt < 6; rt++)
            red[(grp * 6 + rt) * 132 + j] = tanhf(acc[rt]) * w2;
    }
    __syncthreads();

    {
        int wid = tid >> 5, lane = tid & 31;
        float b2 = ab2[0];
#pragma unroll
        for (int u = 0; u < 2; u++) {
            int rt = wid * 2 + u;
            if (rt < 12) {
                float s = red[rt * 132 + lane] + red[rt * 132 + lane + 32]
                        + red[rt * 132 + lane + 64] + red[rt * 132 + lane + 96];
#pragma unroll
                for (int off = 16; off; off >>= 1) s += __shfl_xor_sync(0xffffffffu, s, off);
                if (lane == 0)
                    lgs[rt] = g_hit3[(size_t)row0 * 3 + rt] ? (s + b2) : NEG_BIG;
            }
        }
    }
    __syncthreads();
    if (tid < 4) {
        float l0 = lgs[tid * 3 + 0], l1 = lgs[tid * 3 + 1], l2 = lgs[tid * 3 + 2];
        float m = fmaxf(l0, fmaxf(l1, l2));
        float e0 = expf(l0 - m), e1 = expf(l1 - m), e2 = expf(l2 - m);
        float inv = 1.f / (e0 + e1 + e2);
        attn_s[tid][0] = e0 * inv; attn_s[tid][1] = e1 * inv; attn_s[tid][2] = e2 * inv;
    }
    __syncthreads();

    for (int idx = tid; idx < 4 * CDIM; idx += 256) {
        int r = idx >> 9, c = idx & 511;
        float val;
        if (c < EDIM) {
            val = S[(size_t)(row0 + r) * EDIM + c];
        } else {
            int d = c - EDIM;
            val = attn_s[r][0] * retr[(r * 3 + 0) * 256 + d]
                + attn_s[r][1] * retr[(r * 3 + 1) * 256 + d]
                + attn_s[r][2] * retr[(r * 3 + 2) * 256 + d];
        }
        g_comb[(size_t)(row0 + r) * CDIM + c] = val;
    }
}

// ---------------- K7: g1 = relu(comb @ i_w1 + i_b1)  (8 rows/CTA) ----------------
__global__ void __launch_bounds__(256) k7_int1(const float* __restrict__ W,
                                               const float* __restrict__ b) {
    __shared__ float xs[CDIM * 10];   // 20 KB
    int r0 = blockIdx.x * 8;
    int tid = threadIdx.x;
    int j = blockIdx.y * 256 + tid;
    for (int i = tid; i < 8 * CDIM; i += 256) {
        int r = i >> 9, c = i & 511;
        xs[c * 10 + r] = g_comb[(size_t)(r0 + r) * CDIM + c];
    }
    __syncthreads();
    float bj = b[j];
    ull acc[4];
#pragma unroll
    for (int p = 0; p < 4; p++) acc[p] = pack2(bj, bj);
    for (int k = 0; k < CDIM; k += 8) {
        float w[8];
#pragma unroll
        for (int u = 0; u < 8; u++) w[u] = W[(k + u) * IH + j];
#pragma unroll
        for (int u = 0; u < 8; u++) {
            ull wp = pack2(w[u], w[u]);
#pragma unroll
            for (int p = 0; p < 4; p++)
                fma2(acc[p], lds64(xs + (k + u) * 10 + 2 * p), wp);
        }
    }
#pragma unroll
    for (int p = 0; p < 4; p++) {
        float2 f = unpack2(acc[p]);
        g_g1[(size_t)(r0 + 2 * p) * IH + j]     = fmaxf(f.x, 0.f);
        g_g1[(size_t)(r0 + 2 * p + 1) * IH + j] = fmaxf(f.y, 0.f);
    }
}

// ---------------- K8: out = g1 @ i_w2 + i_b2  (4 rows/CTA) ----------------
__global__ void __launch_bounds__(256) k8_int2(const float* __restrict__ W,
                                               const float* __restrict__ b,
                                               float* __restrict__ out) {
    __shared__ float xs[IH * 6];   // 12 KB
    int r0 = blockIdx.x * 4;
    int tid = threadIdx.x;          // j = tid, ODIM == 256
    for (int i = tid; i < 4 * IH; i += 256) {
        int r = i >> 9, c = i & 511;
        xs[c * 6 + r] = g_g1[(size_t)(r0 + r) * IH + c];
    }
    __syncthreads();
    float bj = b[tid];
    ull acc[2];
#pragma unroll
    for (int p = 0; p < 2; p++) acc[p] = pack2(bj, bj);
    for (int k = 0; k < IH; k += 8) {
        float w[8];
#pragma unroll
        for (int u = 0; u < 8; u++) w[u] = W[(k + u) * ODIM + tid];
#pragma unroll
        for (int u = 0; u < 8; u++) {
            ull wp = pack2(w[u], w[u]);
#pragma unroll
            for (int p = 0; p < 2; p++)
                fma2(acc[p], lds64(xs + (k + u) * 6 + 2 * p), wp);
        }
    }
#pragma unroll
    for (int p = 0; p < 2; p++) {
        float2 f = unpack2(acc[p]);
        out[(size_t)(r0 + 2 * p) * ODIM + tid]     = f.x;
        out[(size_t)(r0 + 2 * p + 1) * ODIM + tid] = f.y;
    }
}

// ---------------- K9: fallback path for rows with no hit (rare/never) ----------------
__global__ void k9_fallback(const float* __restrict__ S,
                            const float* __restrict__ fw1, const float* __restrict__ fb1,
                            const float* __restrict__ fw2, const float* __restrict__ fb2,
                            float* __restrict__ out) {
    int row = blockIdx.x;
    if (g_anyhit[row]) return;
    __shared__ float xs[EDIM];
    __shared__ float h[IH];
    int tid = threadIdx.x;  // 256
    for (int i = tid; i < EDIM; i += 256) xs[i] = S[(size_t)row * EDIM + i];
    __syncthreads();
    for (int j = tid; j < IH; j += 256) {
        float a = fb1[j];
        for (int k = 0; k < EDIM; k++) a = fmaf(xs[k], fw1[k * IH + j], a);
        h[j] = fmaxf(a, 0.f);
    }
    __syncthreads();
    {
        int j = tid;
        float a = fb2[j];
        for (int k = 0; k < IH; k++) a = fmaf(h[k], fw2[k * ODIM + j], a);
        out[(size_t)row * ODIM + j] = a;
    }
}

// ---------------- launch ----------------
extern "C" void kernel_launch(void* const* d_in, const int* in_sizes, int n_in,
                              void* d_out, int out_size) {
    const float* S    = (const float*)d_in[0];
    const float* keys = (const float*)d_in[1];
    const float* vals = (const float*)d_in[2];
    const float* kw1  = (const float*)d_in[3];
    const float* kb1  = (const float*)d_in[4];
    const float* kw2  = (const float*)d_in[5];
    const float* kb2  = (const float*)d_in[6];
    const float* aw1  = (const float*)d_in[7];
    const float* ab1  = (const float*)d_in[8];
    const float* aw2  = (const float*)d_in[9];
    const float* ab2  = (const float*)d_in[10];
    const float* iw1  = (const float*)d_in[11];
    const float* ib1  = (const float*)d_in[12];
    const float* iw2  = (const float*)d_in[13];
    const float* ib2  = (const float*)d_in[14];
    const float* fw1  = (const float*)d_in[15];
    const float* fb1  = (const float*)d_in[16];
    const float* fw2  = (const float*)d_in[17];
    const float* fb2  = (const float*)d_in[18];
    float* out = (float*)d_out;

    static int configured = 0;
    if (!configured) {
        cudaFuncSetAttribute(k4_gemm, cudaFuncAttributeMaxDynamicSharedMemorySize, SMEM_K4);
        configured = 1;
    }

    kc_keys<<<MKEYS / 8, 256>>>(keys);
    k12<<<BQ / 4, 256>>>(S, kw1, kb1, kw2, kb2, aw1, ab1);
    k4_gemm<<<dim3(GX, BQ / 128), 256, SMEM_K4>>>();
    k5sel<<<BQ, 128>>>(keys, vals);
    k6m<<<BQ / 4, 256, K6M_SMEM>>>(S, aw1, aw2, ab2);
    k7_int1<<<dim3(BQ / 8, 2), 256>>>(iw1, ib1);
    k8_int2<<<BQ / 4, 256>>>(iw2, ib2, out);
    k9_fallback<<<BQ, 256>>>(S, fw1, fb1, fw2, fb2, out);
}

// round 13
// speedup vs baseline: 1.0720x; 1.0360x over previous
#include <cuda_runtime.h>
#include <cuda_bf16.h>
#include <math.h>
#include <float.h>
#include <stdint.h>

#define BQ     2048
#define MKEYS  131072
#define EDIM   256
#define KDIM   128
#define VDIM   256
#define ODIM   256
#define H1     512
#define AH     128
#define IH     512
#define CDIM   (EDIM + VDIM)   // 512
#define GX     128             // CTAs along key dim in k4
#define NT     8               // key tiles (128 keys) per CTA
#define NCAND  (GX * 2 * 2)    // 512 candidates per row (top-2 per (bx, wn))
#define NEG_BIG (-1e9f)

// ---------------- scratch (static device globals; no allocation) ----------------
__device__ float g_qn[BQ * KDIM];                           // 1 MB
__device__ __align__(16) __nv_bfloat16 g_qhi[BQ * KDIM];    // 512 KB
__device__ __align__(16) __nv_bfloat16 g_khi[MKEYS * KDIM]; // 32 MB
__device__ float g_invn[MKEYS];                             // 0.5 MB
__device__ float g_p3val[BQ * NCAND];                       // 4.2 MB (idx reconstructed from payload)
__device__ float g_sterm[BQ * AH];                          // 1 MB
__device__ float g_retr[BQ * 3 * VDIM];                     // 6 MB
__device__ int   g_hit3[BQ * 3];
__device__ int   g_anyhit[BQ];
__device__ float g_comb[BQ * CDIM];                         // 4 MB
__device__ float g_g1[BQ * IH];                             // 4 MB

// ================= helpers =================
typedef unsigned long long ull;
__device__ __forceinline__ ull pack2(float x, float y) {
    ull r; asm("mov.b64 %0, {%1, %2};" : "=l"(r) : "f"(x), "f"(y)); return r;
}
__device__ __forceinline__ void fma2(ull& d, ull a, ull b) {
    asm("fma.rn.f32x2 %0, %1, %2, %0;" : "+l"(d) : "l"(a), "l"(b));
}
__device__ __forceinline__ float2 unpack2(ull v) {
    float2 f; asm("mov.b64 {%0, %1}, %2;" : "=f"(f.x), "=f"(f.y) : "l"(v)); return f;
}
__device__ __forceinline__ ull lds64(const float* p) { return *(const ull*)p; }
__device__ __forceinline__ uint32_t smem_u32(const void* p) {
    uint32_t a;
    asm("{ .reg .u64 t; cvta.to.shared.u64 t, %1; cvt.u32.u64 %0, t; }" : "=r"(a) : "l"(p));
    return a;
}
__device__ __forceinline__ void ldsm4(uint32_t* r, uint32_t addr) {
    asm volatile("ldmatrix.sync.aligned.m8n8.x4.shared.b16 {%0,%1,%2,%3}, [%4];"
                 : "=r"(r[0]), "=r"(r[1]), "=r"(r[2]), "=r"(r[3]) : "r"(addr));
}
__device__ __forceinline__ void mma16816(float* d, const uint32_t* a, const uint32_t* b) {
    asm volatile(
        "mma.sync.aligned.m16n8k16.row.col.f32.bf16.bf16.f32 "
        "{%0,%1,%2,%3}, {%4,%5,%6,%7}, {%8,%9}, {%0,%1,%2,%3};"
        : "+f"(d[0]), "+f"(d[1]), "+f"(d[2]), "+f"(d[3])
        : "r"(a[0]), "r"(a[1]), "r"(a[2]), "r"(a[3]), "r"(b[0]), "r"(b[1]));
}
__device__ __forceinline__ void cp16(uint32_t saddr, const void* gaddr) {
    asm volatile("cp.async.cg.shared.global [%0], [%1], 16;" :: "r"(saddr), "l"(gaddr));
}
#define CP_COMMIT() asm volatile("cp.async.commit_group;" ::: "memory")
#define CP_WAIT0()  asm volatile("cp.async.wait_group 0;" ::: "memory")

__device__ __forceinline__ void ins2(float& v0, float& v1, float p) {
    float t = fminf(v0, p);
    v0 = fmaxf(v0, p);
    v1 = fmaxf(v1, t);
}
__device__ __forceinline__ void ins3(float& v0, float& v1, float& v2, float p) {
    float t1 = fminf(v0, p); v0 = fmaxf(v0, p);
    float t2 = fminf(v1, t1); v1 = fmaxf(v1, t1);
    v2 = fmaxf(v2, t2);
}
__device__ __forceinline__ bool better(float v, int i, float V, int I) {
    return (v > V) || (v == V && (unsigned)i < (unsigned)I);
}

// ---------------- KC: key inverse norms + normalized bf16 keys ----------------
__global__ void kc_keys(const float* __restrict__ keys) {
    int row = blockIdx.x * 8 + (threadIdx.x >> 5);
    int lane = threadIdx.x & 31;
    float4 v = ((const float4*)keys)[(size_t)row * 32 + lane];
    float s = v.x * v.x + v.y * v.y + v.z * v.z + v.w * v.w;
#pragma unroll
    for (int o = 16; o > 0; o >>= 1) s += __shfl_xor_sync(0xffffffffu, s, o);
    float in = 1.f / fmaxf(sqrtf(s), 1e-8f);
    if (lane == 0) g_invn[row] = in;
    unsigned short hb[4];
    hb[0] = __bfloat16_as_ushort(__float2bfloat16(v.x * in));
    hb[1] = __bfloat16_as_ushort(__float2bfloat16(v.y * in));
    hb[2] = __bfloat16_as_ushort(__float2bfloat16(v.z * in));
    hb[3] = __bfloat16_as_ushort(__float2bfloat16(v.w * in));
    uint2 uh;
    uh.x = (uint32_t)hb[0] | ((uint32_t)hb[1] << 16);
    uh.y = (uint32_t)hb[2] | ((uint32_t)hb[3] << 16);
    ((uint2*)g_khi)[(size_t)row * 32 + lane] = uh;
}

// ---------------- K12: fused key-encoder MLP + normalize + sterm (4 rows/CTA) ----------------
__global__ void __launch_bounds__(256) k12(const float* __restrict__ S,
                                           const float* __restrict__ kw1, const float* __restrict__ kb1,
                                           const float* __restrict__ kw2, const float* __restrict__ kb2,
                                           const float* __restrict__ aw1, const float* __restrict__ ab1) {
    __shared__ float sx[EDIM * 6];        // S transposed [c][r], 6 KB
    __shared__ float sh[H1 * 6];          // hidden transposed, 12 KB
    __shared__ float part[2][4][128];     // split-K partials, 4 KB
    __shared__ float qs[4][128];
    __shared__ float sinv[4];
    const int r0 = blockIdx.x * 4;
    const int tid = threadIdx.x;
    const int j128 = tid & 127, half = tid >> 7;

    for (int i = tid; i < 4 * EDIM; i += 256) {
        int r = i >> 8, c = i & 255;
        sx[c * 6 + r] = S[(size_t)(r0 + r) * EDIM + c];
    }
    __syncthreads();

    // phase 1: hidden = relu(S @ kw1 + kb1) -> sh (each thread 2 output cols)
#pragma unroll 1
    for (int jj = 0; jj < 2; jj++) {
        int j = jj * 256 + tid;
        float bj = kb1[j];
        ull acc[2];
        acc[0] = pack2(bj, bj); acc[1] = acc[0];
        for (int k = 0; k < EDIM; k += 8) {
            float w[8];
#pragma unroll
            for (int u = 0; u < 8; u++) w[u] = kw1[(k + u) * H1 + j];
#pragma unroll
            for (int u = 0; u < 8; u++) {
                ull wp = pack2(w[u], w[u]);
                fma2(acc[0], lds64(sx + (k + u) * 6 + 0), wp);
                fma2(acc[1], lds64(sx + (k + u) * 6 + 2), wp);
            }
        }
#pragma unroll
        for (int p = 0; p < 2; p++) {
            float2 f = unpack2(acc[p]);
            sh[j * 6 + 2 * p]     = fmaxf(f.x, 0.f);
            sh[j * 6 + 2 * p + 1] = fmaxf(f.y, 0.f);
        }
    }

    // phase S: sterm partials = S @ aw1_top (split-K over 256)
    {
        ull acc[2] = { 0ull, 0ull };
        int kbeg = half * 128;
        for (int k = kbeg; k < kbeg + 128; k += 8) {
            float w[8];
#pragma unroll
            for (int u = 0; u < 8; u++) w[u] = aw1[(k + u) * AH + j128];
#pragma unroll
            for (int u = 0; u < 8; u++) {
                ull wp = pack2(w[u], w[u]);
                fma2(acc[0], lds64(sx + (k + u) * 6 + 0), wp);
                fma2(acc[1], lds64(sx + (k + u) * 6 + 2), wp);
            }
        }
#pragma unroll
        for (int p = 0; p < 2; p++) {
            float2 f = unpack2(acc[p]);
            part[half][2 * p][j128]     = f.x;
            part[half][2 * p + 1][j128] = f.y;
        }
    }
    __syncthreads();
    if (tid < 128) {
        float bj = ab1[tid];
#pragma unroll
        for (int r = 0; r < 4; r++)
            g_sterm[(size_t)(r0 + r) * AH + tid] = part[0][r][tid] + part[1][r][tid] + bj;
    }
    __syncthreads();

    // phase 2: query = hidden @ kw2 (split-K over 512)
    {
        ull acc[2] = { 0ull, 0ull };
        int kbeg = half * 256;
        for (int k = kbeg; k < kbeg + 256; k += 8) {
            float w[8];
#pragma unroll
            for (int u = 0; u < 8; u++) w[u] = kw2[(k + u) * KDIM + j128];
#pragma unroll
            for (int u = 0; u < 8; u++) {
                ull wp = pack2(w[u], w[u]);
                fma2(acc[0], lds64(sh + (k + u) * 6 + 0), wp);
                fma2(acc[1], lds64(sh + (k + u) * 6 + 2), wp);
            }
        }
#pragma unroll
        for (int p = 0; p < 2; p++) {
            float2 f = unpack2(acc[p]);
            part[half][2 * p][j128]     = f.x;
            part[half][2 * p + 1][j128] = f.y;
        }
    }
    __syncthreads();
    if (tid < 128) {
        float bj = kb2[tid];
#pragma unroll
        for (int r = 0; r < 4; r++)
            qs[r][tid] = part[0][r][tid] + part[1][r][tid] + bj;
    }
    __syncthreads();
    {
        int wid = tid >> 5, lane = tid & 31;
        if (wid < 4) {
            float a0 = qs[wid][lane],      a1 = qs[wid][lane + 32];
            float a2 = qs[wid][lane + 64], a3 = qs[wid][lane + 96];
            float s = a0 * a0 + a1 * a1 + a2 * a2 + a3 * a3;
#pragma unroll
            for (int off = 16; off; off >>= 1) s += __shfl_xor_sync(0xffffffffu, s, off);
            if (lane == 0) sinv[wid] = 1.f / fmaxf(sqrtf(s), 1e-8f);
        }
    }
    __syncthreads();
    for (int i = tid; i < 4 * KDIM; i += 256) {
        int r = i >> 7, c = i & 127;
        float x = qs[r][c] * sinv[r];
        g_qn[(size_t)(r0 + r) * KDIM + c] = x;
        g_qhi[(size_t)(r0 + r) * KDIM + c] = __float2bfloat16(x);
    }
}

// ---------------- K4: bf16 HMMA GEMM + running per-lane top-2 (val-only output) ----------------
#define AROW   136
#define TILEB  (128 * AROW * 2)     // 34816
#define SMEM_K4 (3 * TILEB)         // 104448

__device__ __forceinline__ void load_tile_cp(uint32_t sdst, const __nv_bfloat16* __restrict__ g,
                                             int grow0, int tid) {
#pragma unroll
    for (int i = 0; i < 8; i++) {
        int idx = i * 256 + tid;
        int r = idx >> 4, c = idx & 15;
        cp16(sdst + r * (AROW * 2) + c * 16, (const void*)(g + (size_t)(grow0 + r) * KDIM + c * 8));
    }
}

__global__ void __launch_bounds__(256, 2) k4_gemm() {
    extern __shared__ char smem[];
    const uint32_t sb = smem_u32(smem);
    const uint32_t sA = sb, sB0 = sb + TILEB, sB1 = sb + 2 * TILEB;
    const int tid = threadIdx.x;
    const int lane = tid & 31, w = tid >> 5;
    const int wm = w & 3, wn = w >> 2;       // warp grid 4M x 2N
    const int row0 = blockIdx.y * 128;
    const int bx = blockIdx.x;
    const int m0 = wm * 32;

    uint32_t aAddr[2];
#pragma unroll
    for (int f = 0; f < 2; f++)
        aAddr[f] = sA + (uint32_t)(((m0 + f * 16 + (lane & 15)) * AROW + ((lane >> 4) & 1) * 8) * 2);
    const uint32_t bLane = (uint32_t)(((((lane & 7) + ((lane >> 4) << 3)) * AROW) + ((lane >> 3) & 1) * 8) * 2);

    load_tile_cp(sA, g_qhi, row0, tid);
    load_tile_cp(sB0, g_khi, bx * 128, tid);
    CP_COMMIT();
    CP_WAIT0();
    __syncthreads();

    float tv0[4], tv1[4];
#pragma unroll
    for (int r = 0; r < 4; r++) { tv0[r] = -FLT_MAX; tv1[r] = -FLT_MAX; }
    const unsigned qb1 = (unsigned)((lane & 3) << 1);

    for (int i = 0; i < NT; i++) {
        const uint32_t sBuf = (i & 1) ? sB1 : sB0;
        if (i + 1 < NT) {
            load_tile_cp((i & 1) ? sB0 : sB1, g_khi, ((i + 1) * GX + bx) * 128, tid);
        }
        CP_COMMIT();

        float acc[2][8][4];
#pragma unroll
        for (int f = 0; f < 2; f++)
#pragma unroll
            for (int j8 = 0; j8 < 8; j8++)
#pragma unroll
                for (int q = 0; q < 4; q++) acc[f][j8][q] = 0.f;

#pragma unroll
        for (int s = 0; s < 8; s++) {
            uint32_t a0[4], a1[4];
            ldsm4(a0, aAddr[0] + s * 32);
            ldsm4(a1, aAddr[1] + s * 32);
#pragma unroll
            for (int g = 0; g < 4; g++) {
                uint32_t bf[4];
                ldsm4(bf, sBuf + bLane + (uint32_t)(((wn * 4 + g) * 16) * (AROW * 2)) + s * 32);
                mma16816(acc[0][2 * g],     a0, bf);
                mma16816(acc[0][2 * g + 1], a0, bf + 2);
                mma16816(acc[1][2 * g],     a1, bf);
                mma16816(acc[1][2 * g + 1], a1, bf + 2);
            }
        }

        // running top-2: pack 9-bit payload (tile i: 3b, col-in-64: 6b) into mantissa
        const unsigned ibase = (unsigned)(i << 6) | qb1;
#pragma unroll
        for (int f = 0; f < 2; f++)
#pragma unroll
            for (int j8 = 0; j8 < 8; j8++)
#pragma unroll
                for (int q = 0; q < 4; q++) {
                    int ridx = f * 2 + (q >> 1);
                    unsigned pay = ibase | ((unsigned)j8 << 3) | (unsigned)(q & 1);
                    float p = __uint_as_float((__float_as_uint(acc[f][j8][q]) & 0xFFFFFE00u) | pay);
                    ins2(tv0[ridx], tv1[ridx], p);
                }

        CP_WAIT0();
        __syncthreads();
    }

    // merge across quad
#pragma unroll
    for (int off = 1; off <= 2; off <<= 1) {
#pragma unroll
        for (int r = 0; r < 4; r++) {
            float u0 = __shfl_xor_sync(0xffffffffu, tv0[r], off);
            float u1 = __shfl_xor_sync(0xffffffffu, tv1[r], off);
            ins2(tv0[r], tv1[r], u0);
            ins2(tv0[r], tv1[r], u1);
        }
    }
    if ((lane & 3) == 0) {
        const int r_lo = lane >> 2;
#pragma unroll
        for (int r = 0; r < 4; r++) {
            int grow = row0 + m0 + (r >> 1) * 16 + r_lo + (r & 1) * 8;
            size_t base = (((size_t)grow * GX + bx) * 2 + wn) * 2;
            g_p3val[base + 0] = tv0[r];
            g_p3val[base + 1] = tv1[r];
        }
    }
}

// ---------------- K5SEL: warp-local top-8 (idx reconstructed) -> rescore -> top-3 + gather ----------------
__global__ void __launch_bounds__(128) k5sel(const float* __restrict__ keys,
                                             const float* __restrict__ values) {
    int row = blockIdx.x;
    int tid = threadIdx.x;  // 128
    int lane = tid & 31, w = tid >> 5;
    __shared__ float qrow[KDIM];
    __shared__ float wcval[4][8];
    __shared__ int   wcid[4][8];
    __shared__ int   c_idx[8];
    __shared__ float c_val[8];
    __shared__ int   sel_s[3];
    __shared__ int   hit_s[3];

    qrow[tid] = g_qn[(size_t)row * KDIM + tid];

    // warp w owns candidates [w*128, w*128+128); idx reconstructed from position + payload
    float v[4]; int id[4];
#pragma unroll
    for (int t = 0; t < 4; t++) {
        int e = w * 128 + t * 32 + lane;
        float val = g_p3val[(size_t)row * NCAND + e];
        v[t] = val;
        unsigned pay = __float_as_uint(val) & 511u;
        int bx = e >> 2, wnn = (e >> 1) & 1;
        id[t] = ((int)(pay >> 6) * GX + bx) * 128 + wnn * 64 + (int)(pay & 63u);
    }
    // warp-local top-8 (8 shfl-argmax rounds, no block syncs)
#pragma unroll 1
    for (int r = 0; r < 8; r++) {
        float lv = v[0]; int lt = 0;
#pragma unroll
        for (int t = 1; t < 4; t++) if (v[t] > lv) { lv = v[t]; lt = t; }
        int lid = id[lt];
        int lpos = lt * 32 + lane;
#pragma unroll
        for (int off = 16; off; off >>= 1) {
            float ov = __shfl_xor_sync(0xffffffffu, lv, off);
            int   oi = __shfl_xor_sync(0xffffffffu, lid, off);
            int   op = __shfl_xor_sync(0xffffffffu, lpos, off);
            if (ov > lv || (ov == lv && op < lpos)) { lv = ov; lid = oi; lpos = op; }
        }
        if ((lpos & 31) == lane) v[lpos >> 5] = -FLT_MAX;   // winner lane invalidates
        if (lane == 0) { wcval[w][r] = lv; wcid[w][r] = lid; }
    }
    __syncthreads();

    // warp 0 merges 4x8 -> global top-8
    if (w == 0) {
        float mv = wcval[lane >> 3][lane & 7];
        int   mi = wcid[lane >> 3][lane & 7];
#pragma unroll 1
        for (int r = 0; r < 8; r++) {
            float bv = mv; int bi = mi; int bp = lane;
#pragma unroll
            for (int off = 16; off; off >>= 1) {
                float ov = __shfl_xor_sync(0xffffffffu, bv, off);
                int   oi = __shfl_xor_sync(0xffffffffu, bi, off);
                int   op = __shfl_xor_sync(0xffffffffu, bp, off);
                if (ov > bv || (ov == bv && op < bp)) { bv = ov; bi = oi; bp = op; }
            }
            if (lane == bp) mv = -FLT_MAX;
            if (lane == 0) c_idx[r] = bi;
        }
    }
    __syncthreads();

    // exact fp32 rescore of 8 candidates
    {
        int c = tid >> 4, l = tid & 15;
        int idx = c_idx[c];
        float part = 0.f;
#pragma unroll
        for (int jj = 0; jj < 8; jj++) {
            int k = l + jj * 16;
            part += qrow[k] * keys[(size_t)idx * KDIM + k];
        }
#pragma unroll
        for (int off = 8; off; off >>= 1) part += __shfl_xor_sync(0xffffffffu, part, off);
        if (l == 0) c_val[c] = part * g_invn[idx];
    }
    __syncthreads();

    if (tid == 0) {
        int used = 0;
#pragma unroll
        for (int k = 0; k < 3; k++) {
            float bv = -FLT_MAX; int bi = 0x7fffffff; int bs = -1;
#pragma unroll
            for (int t = 0; t < 8; t++) {
                if (used & (1 << t)) continue;
                if (better(c_val[t], c_idx[t], bv, bi)) { bv = c_val[t]; bi = c_idx[t]; bs = t; }
            }
            used |= (1 << bs);
            sel_s[k] = bi; hit_s[k] = (bv >= 0.0f);
        }
        g_anyhit[row] = hit_s[0] | hit_s[1] | hit_s[2];
        g_hit3[row * 3 + 0] = hit_s[0];
        g_hit3[row * 3 + 1] = hit_s[1];
        g_hit3[row * 3 + 2] = hit_s[2];
    }
    __syncthreads();

#pragma unroll
    for (int t = 0; t < 3; t++) {
        int idx = sel_s[t];
        for (int d = tid; d < VDIM; d += 128)
            g_retr[((size_t)row * 3 + t) * VDIM + d] = values[(size_t)idx * VDIM + d];
    }
}

// ---------------- K6M: attention + softmax + mem_vec -> g_comb (4 rows/CTA) ----------------
#define K6M_SMEM ((12 * 256 + 12 * 132) * 4)   // 18624 B
__global__ void __launch_bounds__(256) k6m(const float* __restrict__ S,
                                           const float* __restrict__ aw1,
                                           const float* __restrict__ aw2,
                                           const float* __restrict__ ab2) {
    extern __shared__ char dsm[];
    float* retr = (float*)dsm;          // [12][256]
    float* red  = retr + 12 * 256;      // [12][132]
    __shared__ float sterm_s[4 * 128];
    __shared__ float lgs[12];
    __shared__ float attn_s[4][3];

    const int row0 = blockIdx.x * 4;
    const int tid = threadIdx.x;

    for (int idx = tid; idx < 12 * VDIM; idx += 256)
        retr[idx] = g_retr[(size_t)row0 * 3 * VDIM + idx];
    for (int idx = tid; idx < 4 * AH; idx += 256)
        sterm_s[idx] = g_sterm[(size_t)row0 * AH + idx];
    __syncthreads();

    {
        int j = tid & 127, grp = tid >> 7;  // grp handles 6 triples
        float acc[6];
#pragma unroll
        for (int rt = 0; rt < 6; rt++) acc[rt] = sterm_s[((grp * 6 + rt) / 3) * 128 + j];
        for (int k = 0; k < VDIM; k += 2) {
            float w0 = aw1[(EDIM + k) * AH + j];
            float w1 = aw1[(EDIM + k + 1) * AH + j];
#pragma unroll
            for (int rt = 0; rt < 6; rt++) {
                int g = grp * 6 + rt;
                acc[rt] = fmaf(retr[g * 256 + k],     w0, acc[rt]);
                acc[rt] = fmaf(retr[g * 256 + k + 1], w1, acc[rt]);
            }
        }
        float w2 = aw2[j];
#pragma unroll
        for (int rt = 0; rt < 6; rt++)
            red[(grp * 6 + rt) * 132 + j] = tanhf(acc[rt]) * w2;
    }
    __syncthreads();

    {
        int wid = tid >> 5, lane = tid & 31;
        float b2 = ab2[0];
#pragma unroll
        for (int u = 0; u < 2; u++) {
            int rt = wid * 2 + u;
            if (rt < 12) {
                float s = red[rt * 132 + lane] + red[rt * 132 + lane + 32]
                        + red[rt * 132 + lane + 64] + red[rt * 132 + lane + 96];
#pragma unroll
                for (int off = 16; off; off >>= 1) s += __shfl_xor_sync(0xffffffffu, s, off);
                if (lane == 0)
                    lgs[rt] = g_hit3[(size_t)row0 * 3 + rt] ? (s + b2) : NEG_BIG;
            }
        }
    }
    __syncthreads();
    if (tid < 4) {
        float l0 = lgs[tid * 3 + 0], l1 = lgs[tid * 3 + 1], l2 = lgs[tid * 3 + 2];
        float m = fmaxf(l0, fmaxf(l1, l2));
        float e0 = expf(l0 - m), e1 = expf(l1 - m), e2 = expf(l2 - m);
        float inv = 1.f / (e0 + e1 + e2);
        attn_s[tid][0] = e0 * inv; attn_s[tid][1] = e1 * inv; attn_s[tid][2] = e2 * inv;
    }
    __syncthreads();

    for (int idx = tid; idx < 4 * CDIM; idx += 256) {
        int r = idx >> 9, c = idx & 511;
        float val;
        if (c < EDIM) {
            val = S[(size_t)(row0 + r) * EDIM + c];
        } else {
            int d = c - EDIM;
            val = attn_s[r][0] * retr[(r * 3 + 0) * 256 + d]
                + attn_s[r][1] * retr[(r * 3 + 1) * 256 + d]
                + attn_s[r][2] * retr[(r * 3 + 2) * 256 + d];
        }
        g_comb[(size_t)(row0 + r) * CDIM + c] = val;
    }
}

// ---------------- K7: g1 = relu(comb @ i_w1 + i_b1)  (8 rows/CTA) ----------------
__global__ void __launch_bounds__(256) k7_int1(const float* __restrict__ W,
                                               const float* __restrict__ b) {
    __shared__ float xs[CDIM * 10];   // 20 KB
    int r0 = blockIdx.x * 8;
    int tid = threadIdx.x;
    int j = blockIdx.y * 256 + tid;
    for (int i = tid; i < 8 * CDIM; i += 256) {
        int r = i >> 9, c = i & 511;
        xs[c * 10 + r] = g_comb[(size_t)(r0 + r) * CDIM + c];
    }
    __syncthreads();
    float bj = b[j];
    ull acc[4];
#pragma unroll
    for (int p = 0; p < 4; p++) acc[p] = pack2(bj, bj);
    for (int k = 0; k < CDIM; k += 8) {
        float w[8];
#pragma unroll
        for (int u = 0; u < 8; u++) w[u] = W[(k + u) * IH + j];
#pragma unroll
        for (int u = 0; u < 8; u++) {
            ull wp = pack2(w[u], w[u]);
#pragma unroll
            for (int p = 0; p < 4; p++)
                fma2(acc[p], lds64(xs + (k + u) * 10 + 2 * p), wp);
        }
    }
#pragma unroll
    for (int p = 0; p < 4; p++) {
        float2 f = unpack2(acc[p]);
        g_g1[(size_t)(r0 + 2 * p) * IH + j]     = fmaxf(f.x, 0.f);
        g_g1[(size_t)(r0 + 2 * p + 1) * IH + j] = fmaxf(f.y, 0.f);
    }
}

// ---------------- K8: out = g1 @ i_w2 + i_b2  (4 rows/CTA) ----------------
__global__ void __launch_bounds__(256) k8_int2(const float* __restrict__ W,
                                               const float* __restrict__ b,
                                               float* __restrict__ out) {
    __shared__ float xs[IH * 6];   // 12 KB
    int r0 = blockIdx.x * 4;
    int tid = threadIdx.x;          // j = tid, ODIM == 256
    for (int i = tid; i < 4 * IH; i += 256) {
        int r = i >> 9, c = i & 511;
        xs[c * 6 + r] = g_g1[(size_t)(r0 + r) * IH + c];
    }
    __syncthreads();
    float bj = b[tid];
    ull acc[2];
#pragma unroll
    for (int p = 0; p < 2; p++) acc[p] = pack2(bj, bj);
    for (int k = 0; k < IH; k += 8) {
        float w[8];
#pragma unroll
        for (int u = 0; u < 8; u++) w[u] = W[(k + u) * ODIM + tid];
#pragma unroll
        for (int u = 0; u < 8; u++) {
            ull wp = pack2(w[u], w[u]);
#pragma unroll
            for (int p = 0; p < 2; p++)
                fma2(acc[p], lds64(xs + (k + u) * 6 + 2 * p), wp);
        }
    }
#pragma unroll
    for (int p = 0; p < 2; p++) {
        float2 f = unpack2(acc[p]);
        out[(size_t)(r0 + 2 * p) * ODIM + tid]     = f.x;
        out[(size_t)(r0 + 2 * p + 1) * ODIM + tid] = f.y;
    }
}

// ---------------- K9: fallback path for rows with no hit (rare/never) ----------------
__global__ void k9_fallback(const float* __restrict__ S,
                            const float* __restrict__ fw1, const float* __restrict__ fb1,
                            const float* __restrict__ fw2, const float* __restrict__ fb2,
                            float* __restrict__ out) {
    int row = blockIdx.x;
    if (g_anyhit[row]) return;
    __shared__ float xs[EDIM];
    __shared__ float h[IH];
    int tid = threadIdx.x;  // 256
    for (int i = tid; i < EDIM; i += 256) xs[i] = S[(size_t)row * EDIM + i];
    __syncthreads();
    for (int j = tid; j < IH; j += 256) {
        float a = fb1[j];
        for (int k = 0; k < EDIM; k++) a = fmaf(xs[k], fw1[k * IH + j], a);
        h[j] = fmaxf(a, 0.f);
    }
    __syncthreads();
    {
        int j = tid;
        float a = fb2[j];
        for (int k = 0; k < IH; k++) a = fmaf(h[k], fw2[k * ODIM + j], a);
        out[(size_t)row * ODIM + j] = a;
    }
}

// ---------------- launch ----------------
extern "C" void kernel_launch(void* const* d_in, const int* in_sizes, int n_in,
                              void* d_out, int out_size) {
    const float* S    = (const float*)d_in[0];
    const float* keys = (const float*)d_in[1];
    const float* vals = (const float*)d_in[2];
    const float* kw1  = (const float*)d_in[3];
    const float* kb1  = (const float*)d_in[4];
    const float* kw2  = (const float*)d_in[5];
    const float* kb2  = (const float*)d_in[6];
    const float* aw1  = (const float*)d_in[7];
    const float* ab1  = (const float*)d_in[8];
    const float* aw2  = (const float*)d_in[9];
    const float* ab2  = (const float*)d_in[10];
    const float* iw1  = (const float*)d_in[11];
    const float* ib1  = (const float*)d_in[12];
    const float* iw2  = (const float*)d_in[13];
    const float* ib2  = (const float*)d_in[14];
    const float* fw1  = (const float*)d_in[15];
    const float* fb1  = (const float*)d_in[16];
    const float* fw2  = (const float*)d_in[17];
    const float* fb2  = (const float*)d_in[18];
    float* out = (float*)d_out;

    static int configured = 0;
    if (!configured) {
        cudaFuncSetAttribute(k4_gemm, cudaFuncAttributeMaxDynamicSharedMemorySize, SMEM_K4);
        configured = 1;
    }

    kc_keys<<<MKEYS / 8, 256>>>(keys);
    k12<<<BQ / 4, 256>>>(S, kw1, kb1, kw2, kb2, aw1, ab1);
    k4_gemm<<<dim3(GX, BQ / 128), 256, SMEM_K4>>>();
    k5sel<<<BQ, 128>>>(keys, vals);
    k6m<<<BQ / 4, 256, K6M_SMEM>>>(S, aw1, aw2, ab2);
    k7_int1<<<dim3(BQ / 8, 2), 256>>>(iw1, ib1);
    k8_int2<<<BQ / 4, 256>>>(iw2, ib2, out);
    k9_fallback<<<BQ, 256>>>(S, fw1, fb1, fw2, fb2, out);
}

// round 14
// speedup vs baseline: 1.0735x; 1.0015x over previous
#include <cuda_runtime.h>
#include <cuda_bf16.h>
#include <math.h>
#include <float.h>
#include <stdint.h>

#define BQ     2048
#define MKEYS  131072
#define EDIM   256
#define KDIM   128
#define VDIM   256
#define ODIM   256
#define H1     512
#define AH     128
#define IH     512
#define CDIM   (EDIM + VDIM)   // 512
#define GX     128             // CTAs along key dim in k4
#define NT     8               // key tiles (128 keys) per CTA
#define NCAND  (GX * 2 * 2)    // 512 candidates per row (top-2 per (bx, wn))
#define NEG_BIG (-1e9f)

// ---------------- scratch (static device globals; no allocation) ----------------
__device__ float g_qn[BQ * KDIM];                           // 1 MB
__device__ __align__(16) __nv_bfloat16 g_qhi[BQ * KDIM];    // 512 KB
__device__ __align__(16) __nv_bfloat16 g_khi[MKEYS * KDIM]; // 32 MB
__device__ float g_invn[MKEYS];                             // 0.5 MB
__device__ float g_p3val[BQ * NCAND];                       // 4.2 MB (idx reconstructed from payload)
__device__ float g_sterm[BQ * AH];                          // 1 MB
__device__ float g_retr[BQ * 3 * VDIM];                     // 6 MB
__device__ int   g_hit3[BQ * 3];
__device__ int   g_anyhit[BQ];
__device__ float g_comb[BQ * CDIM];                         // 4 MB

// ================= helpers =================
typedef unsigned long long ull;
__device__ __forceinline__ ull pack2(float x, float y) {
    ull r; asm("mov.b64 %0, {%1, %2};" : "=l"(r) : "f"(x), "f"(y)); return r;
}
__device__ __forceinline__ void fma2(ull& d, ull a, ull b) {
    asm("fma.rn.f32x2 %0, %1, %2, %0;" : "+l"(d) : "l"(a), "l"(b));
}
__device__ __forceinline__ float2 unpack2(ull v) {
    float2 f; asm("mov.b64 {%0, %1}, %2;" : "=f"(f.x), "=f"(f.y) : "l"(v)); return f;
}
__device__ __forceinline__ ull lds64(const float* p) { return *(const ull*)p; }
__device__ __forceinline__ uint32_t smem_u32(const void* p) {
    uint32_t a;
    asm("{ .reg .u64 t; cvta.to.shared.u64 t, %1; cvt.u32.u64 %0, t; }" : "=r"(a) : "l"(p));
    return a;
}
__device__ __forceinline__ void ldsm4(uint32_t* r, uint32_t addr) {
    asm volatile("ldmatrix.sync.aligned.m8n8.x4.shared.b16 {%0,%1,%2,%3}, [%4];"
                 : "=r"(r[0]), "=r"(r[1]), "=r"(r[2]), "=r"(r[3]) : "r"(addr));
}
__device__ __forceinline__ void mma16816(float* d, const uint32_t* a, const uint32_t* b) {
    asm volatile(
        "mma.sync.aligned.m16n8k16.row.col.f32.bf16.bf16.f32 "
        "{%0,%1,%2,%3}, {%4,%5,%6,%7}, {%8,%9}, {%0,%1,%2,%3};"
        : "+f"(d[0]), "+f"(d[1]), "+f"(d[2]), "+f"(d[3])
        : "r"(a[0]), "r"(a[1]), "r"(a[2]), "r"(a[3]), "r"(b[0]), "r"(b[1]));
}
__device__ __forceinline__ void cp16(uint32_t saddr, const void* gaddr) {
    asm volatile("cp.async.cg.shared.global [%0], [%1], 16;" :: "r"(saddr), "l"(gaddr));
}
#define CP_COMMIT() asm volatile("cp.async.commit_group;" ::: "memory")
#define CP_WAIT0()  asm volatile("cp.async.wait_group 0;" ::: "memory")

__device__ __forceinline__ void ins2(float& v0, float& v1, float p) {
    float t = fminf(v0, p);
    v0 = fmaxf(v0, p);
    v1 = fmaxf(v1, t);
}
__device__ __forceinline__ bool better(float v, int i, float V, int I) {
    return (v > V) || (v == V && (unsigned)i < (unsigned)I);
}

// ---------------- KC: key inverse norms + normalized bf16 keys ----------------
__global__ void kc_keys(const float* __restrict__ keys) {
    int row = blockIdx.x * 8 + (threadIdx.x >> 5);
    int lane = threadIdx.x & 31;
    float4 v = ((const float4*)keys)[(size_t)row * 32 + lane];
    float s = v.x * v.x + v.y * v.y + v.z * v.z + v.w * v.w;
#pragma unroll
    for (int o = 16; o > 0; o >>= 1) s += __shfl_xor_sync(0xffffffffu, s, o);
    float in = 1.f / fmaxf(sqrtf(s), 1e-8f);
    if (lane == 0) g_invn[row] = in;
    unsigned short hb[4];
    hb[0] = __bfloat16_as_ushort(__float2bfloat16(v.x * in));
    hb[1] = __bfloat16_as_ushort(__float2bfloat16(v.y * in));
    hb[2] = __bfloat16_as_ushort(__float2bfloat16(v.z * in));
    hb[3] = __bfloat16_as_ushort(__float2bfloat16(v.w * in));
    uint2 uh;
    uh.x = (uint32_t)hb[0] | ((uint32_t)hb[1] << 16);
    uh.y = (uint32_t)hb[2] | ((uint32_t)hb[3] << 16);
    ((uint2*)g_khi)[(size_t)row * 32 + lane] = uh;
}

// ---------------- K12: fused key-encoder MLP + normalize + sterm (4 rows/CTA) ----------------
__global__ void __launch_bounds__(256) k12(const float* __restrict__ S,
                                           const float* __restrict__ kw1, const float* __restrict__ kb1,
                                           const float* __restrict__ kw2, const float* __restrict__ kb2,
                                           const float* __restrict__ aw1, const float* __restrict__ ab1) {
    __shared__ float sx[EDIM * 6];        // S transposed [c][r], 6 KB
    __shared__ float sh[H1 * 6];          // hidden transposed, 12 KB
    __shared__ float part[2][4][128];     // split-K partials, 4 KB
    __shared__ float qs[4][128];
    __shared__ float sinv[4];
    const int r0 = blockIdx.x * 4;
    const int tid = threadIdx.x;
    const int j128 = tid & 127, half = tid >> 7;

    for (int i = tid; i < 4 * EDIM; i += 256) {
        int r = i >> 8, c = i & 255;
        sx[c * 6 + r] = S[(size_t)(r0 + r) * EDIM + c];
    }
    __syncthreads();

    // phase 1: hidden = relu(S @ kw1 + kb1) -> sh (each thread 2 output cols)
#pragma unroll 1
    for (int jj = 0; jj < 2; jj++) {
        int j = jj * 256 + tid;
        float bj = kb1[j];
        ull acc[2];
        acc[0] = pack2(bj, bj); acc[1] = acc[0];
        for (int k = 0; k < EDIM; k += 8) {
            float w[8];
#pragma unroll
            for (int u = 0; u < 8; u++) w[u] = kw1[(k + u) * H1 + j];
#pragma unroll
            for (int u = 0; u < 8; u++) {
                ull wp = pack2(w[u], w[u]);
                fma2(acc[0], lds64(sx + (k + u) * 6 + 0), wp);
                fma2(acc[1], lds64(sx + (k + u) * 6 + 2), wp);
            }
        }
#pragma unroll
        for (int p = 0; p < 2; p++) {
            float2 f = unpack2(acc[p]);
            sh[j * 6 + 2 * p]     = fmaxf(f.x, 0.f);
            sh[j * 6 + 2 * p + 1] = fmaxf(f.y, 0.f);
        }
    }

    // phase S: sterm partials = S @ aw1_top (split-K over 256)
    {
        ull acc[2] = { 0ull, 0ull };
        int kbeg = half * 128;
        for (int k = kbeg; k < kbeg + 128; k += 8) {
            float w[8];
#pragma unroll
            for (int u = 0; u < 8; u++) w[u] = aw1[(k + u) * AH + j128];
#pragma unroll
            for (int u = 0; u < 8; u++) {
                ull wp = pack2(w[u], w[u]);
                fma2(acc[0], lds64(sx + (k + u) * 6 + 0), wp);
                fma2(acc[1], lds64(sx + (k + u) * 6 + 2), wp);
            }
        }
#pragma unroll
        for (int p = 0; p < 2; p++) {
            float2 f = unpack2(acc[p]);
            part[half][2 * p][j128]     = f.x;
            part[half][2 * p + 1][j128] = f.y;
        }
    }
    __syncthreads();
    if (tid < 128) {
        float bj = ab1[tid];
#pragma unroll
        for (int r = 0; r < 4; r++)
            g_sterm[(size_t)(r0 + r) * AH + tid] = part[0][r][tid] + part[1][r][tid] + bj;
    }
    __syncthreads();

    // phase 2: query = hidden @ kw2 (split-K over 512)
    {
        ull acc[2] = { 0ull, 0ull };
        int kbeg = half * 256;
        for (int k = kbeg; k < kbeg + 256; k += 8) {
            float w[8];
#pragma unroll
            for (int u = 0; u < 8; u++) w[u] = kw2[(k + u) * KDIM + j128];
#pragma unroll
            for (int u = 0; u < 8; u++) {
                ull wp = pack2(w[u], w[u]);
                fma2(acc[0], lds64(sh + (k + u) * 6 + 0), wp);
                fma2(acc[1], lds64(sh + (k + u) * 6 + 2), wp);
            }
        }
#pragma unroll
        for (int p = 0; p < 2; p++) {
            float2 f = unpack2(acc[p]);
            part[half][2 * p][j128]     = f.x;
            part[half][2 * p + 1][j128] = f.y;
        }
    }
    __syncthreads();
    if (tid < 128) {
        float bj = kb2[tid];
#pragma unroll
        for (int r = 0; r < 4; r++)
            qs[r][tid] = part[0][r][tid] + part[1][r][tid] + bj;
    }
    __syncthreads();
    {
        int wid = tid >> 5, lane = tid & 31;
        if (wid < 4) {
            float a0 = qs[wid][lane],      a1 = qs[wid][lane + 32];
            float a2 = qs[wid][lane + 64], a3 = qs[wid][lane + 96];
            float s = a0 * a0 + a1 * a1 + a2 * a2 + a3 * a3;
#pragma unroll
            for (int off = 16; off; off >>= 1) s += __shfl_xor_sync(0xffffffffu, s, off);
            if (lane == 0) sinv[wid] = 1.f / fmaxf(sqrtf(s), 1e-8f);
        }
    }
    __syncthreads();
    for (int i = tid; i < 4 * KDIM; i += 256) {
        int r = i >> 7, c = i & 127;
        float x = qs[r][c] * sinv[r];
        g_qn[(size_t)(r0 + r) * KDIM + c] = x;
        g_qhi[(size_t)(r0 + r) * KDIM + c] = __float2bfloat16(x);
    }
}

// ---------------- K4: bf16 HMMA GEMM + running per-lane top-2 (val-only output) ----------------
#define AROW   136
#define TILEB  (128 * AROW * 2)     // 34816
#define SMEM_K4 (3 * TILEB)         // 104448

__device__ __forceinline__ void load_tile_cp(uint32_t sdst, const __nv_bfloat16* __restrict__ g,
                                             int grow0, int tid) {
#pragma unroll
    for (int i = 0; i < 8; i++) {
        int idx = i * 256 + tid;
        int r = idx >> 4, c = idx & 15;
        cp16(sdst + r * (AROW * 2) + c * 16, (const void*)(g + (size_t)(grow0 + r) * KDIM + c * 8));
    }
}

__global__ void __launch_bounds__(256, 2) k4_gemm() {
    extern __shared__ char smem[];
    const uint32_t sb = smem_u32(smem);
    const uint32_t sA = sb, sB0 = sb + TILEB, sB1 = sb + 2 * TILEB;
    const int tid = threadIdx.x;
    const int lane = tid & 31, w = tid >> 5;
    const int wm = w & 3, wn = w >> 2;       // warp grid 4M x 2N
    const int row0 = blockIdx.y * 128;
    const int bx = blockIdx.x;
    const int m0 = wm * 32;

    uint32_t aAddr[2];
#pragma unroll
    for (int f = 0; f < 2; f++)
        aAddr[f] = sA + (uint32_t)(((m0 + f * 16 + (lane & 15)) * AROW + ((lane >> 4) & 1) * 8) * 2);
    const uint32_t bLane = (uint32_t)(((((lane & 7) + ((lane >> 4) << 3)) * AROW) + ((lane >> 3) & 1) * 8) * 2);

    load_tile_cp(sA, g_qhi, row0, tid);
    load_tile_cp(sB0, g_khi, bx * 128, tid);
    CP_COMMIT();
    CP_WAIT0();
    __syncthreads();

    float tv0[4], tv1[4];
#pragma unroll
    for (int r = 0; r < 4; r++) { tv0[r] = -FLT_MAX; tv1[r] = -FLT_MAX; }
    const unsigned qb1 = (unsigned)((lane & 3) << 1);

    for (int i = 0; i < NT; i++) {
        const uint32_t sBuf = (i & 1) ? sB1 : sB0;
        if (i + 1 < NT) {
            load_tile_cp((i & 1) ? sB0 : sB1, g_khi, ((i + 1) * GX + bx) * 128, tid);
        }
        CP_COMMIT();

        float acc[2][8][4];
#pragma unroll
        for (int f = 0; f < 2; f++)
#pragma unroll
            for (int j8 = 0; j8 < 8; j8++)
#pragma unroll
                for (int q = 0; q < 4; q++) acc[f][j8][q] = 0.f;

#pragma unroll
        for (int s = 0; s < 8; s++) {
            uint32_t a0[4], a1[4];
            ldsm4(a0, aAddr[0] + s * 32);
            ldsm4(a1, aAddr[1] + s * 32);
#pragma unroll
            for (int g = 0; g < 4; g++) {
                uint32_t bf[4];
                ldsm4(bf, sBuf + bLane + (uint32_t)(((wn * 4 + g) * 16) * (AROW * 2)) + s * 32);
                mma16816(acc[0][2 * g],     a0, bf);
                mma16816(acc[0][2 * g + 1], a0, bf + 2);
                mma16816(acc[1][2 * g],     a1, bf);
                mma16816(acc[1][2 * g + 1], a1, bf + 2);
            }
        }

        // running top-2: pack 9-bit payload (tile i: 3b, col-in-64: 6b) into mantissa
        const unsigned ibase = (unsigned)(i << 6) | qb1;
#pragma unroll
        for (int f = 0; f < 2; f++)
#pragma unroll
            for (int j8 = 0; j8 < 8; j8++)
#pragma unroll
                for (int q = 0; q < 4; q++) {
                    int ridx = f * 2 + (q >> 1);
                    unsigned pay = ibase | ((unsigned)j8 << 3) | (unsigned)(q & 1);
                    float p = __uint_as_float((__float_as_uint(acc[f][j8][q]) & 0xFFFFFE00u) | pay);
                    ins2(tv0[ridx], tv1[ridx], p);
                }

        CP_WAIT0();
        __syncthreads();
    }

    // merge across quad
#pragma unroll
    for (int off = 1; off <= 2; off <<= 1) {
#pragma unroll
        for (int r = 0; r < 4; r++) {
            float u0 = __shfl_xor_sync(0xffffffffu, tv0[r], off);
            float u1 = __shfl_xor_sync(0xffffffffu, tv1[r], off);
            ins2(tv0[r], tv1[r], u0);
            ins2(tv0[r], tv1[r], u1);
        }
    }
    if ((lane & 3) == 0) {
        const int r_lo = lane >> 2;
#pragma unroll
        for (int r = 0; r < 4; r++) {
            int grow = row0 + m0 + (r >> 1) * 16 + r_lo + (r & 1) * 8;
            size_t base = (((size_t)grow * GX + bx) * 2 + wn) * 2;
            g_p3val[base + 0] = tv0[r];
            g_p3val[base + 1] = tv1[r];
        }
    }
}

// ---------------- K5SEL: warp-local top-8 (idx reconstructed) -> rescore -> top-3 + gather ----------------
__global__ void __launch_bounds__(128) k5sel(const float* __restrict__ keys,
                                             const float* __restrict__ values) {
    int row = blockIdx.x;
    int tid = threadIdx.x;  // 128
    int lane = tid & 31, w = tid >> 5;
    __shared__ float qrow[KDIM];
    __shared__ float wcval[4][8];
    __shared__ int   wcid[4][8];
    __shared__ int   c_idx[8];
    __shared__ float c_val[8];
    __shared__ int   sel_s[3];
    __shared__ int   hit_s[3];

    qrow[tid] = g_qn[(size_t)row * KDIM + tid];

    // warp w owns candidates [w*128, w*128+128); idx reconstructed from position + payload
    float v[4]; int id[4];
#pragma unroll
    for (int t = 0; t < 4; t++) {
        int e = w * 128 + t * 32 + lane;
        float val = g_p3val[(size_t)row * NCAND + e];
        v[t] = val;
        unsigned pay = __float_as_uint(val) & 511u;
        int bx = e >> 2, wnn = (e >> 1) & 1;
        id[t] = ((int)(pay >> 6) * GX + bx) * 128 + wnn * 64 + (int)(pay & 63u);
    }
    // warp-local top-8 (8 shfl-argmax rounds, no block syncs)
#pragma unroll 1
    for (int r = 0; r < 8; r++) {
        float lv = v[0]; int lt = 0;
#pragma unroll
        for (int t = 1; t < 4; t++) if (v[t] > lv) { lv = v[t]; lt = t; }
        int lid = id[lt];
        int lpos = lt * 32 + lane;
#pragma unroll
        for (int off = 16; off; off >>= 1) {
            float ov = __shfl_xor_sync(0xffffffffu, lv, off);
            int   oi = __shfl_xor_sync(0xffffffffu, lid, off);
            int   op = __shfl_xor_sync(0xffffffffu, lpos, off);
            if (ov > lv || (ov == lv && op < lpos)) { lv = ov; lid = oi; lpos = op; }
        }
        if ((lpos & 31) == lane) v[lpos >> 5] = -FLT_MAX;   // winner lane invalidates
        if (lane == 0) { wcval[w][r] = lv; wcid[w][r] = lid; }
    }
    __syncthreads();

    // warp 0 merges 4x8 -> global top-8
    if (w == 0) {
        float mv = wcval[lane >> 3][lane & 7];
        int   mi = wcid[lane >> 3][lane & 7];
#pragma unroll 1
        for (int r = 0; r < 8; r++) {
            float bv = mv; int bi = mi; int bp = lane;
#pragma unroll
            for (int off = 16; off; off >>= 1) {
                float ov = __shfl_xor_sync(0xffffffffu, bv, off);
                int   oi = __shfl_xor_sync(0xffffffffu, bi, off);
                int   op = __shfl_xor_sync(0xffffffffu, bp, off);
                if (ov > bv || (ov == bv && op < bp)) { bv = ov; bi = oi; bp = op; }
            }
            if (lane == bp) mv = -FLT_MAX;
            if (lane == 0) c_idx[r] = bi;
        }
    }
    __syncthreads();

    // exact fp32 rescore of 8 candidates
    {
        int c = tid >> 4, l = tid & 15;
        int idx = c_idx[c];
        float part = 0.f;
#pragma unroll
        for (int jj = 0; jj < 8; jj++) {
            int k = l + jj * 16;
            part += qrow[k] * keys[(size_t)idx * KDIM + k];
        }
#pragma unroll
        for (int off = 8; off; off >>= 1) part += __shfl_xor_sync(0xffffffffu, part, off);
        if (l == 0) c_val[c] = part * g_invn[idx];
    }
    __syncthreads();

    if (tid == 0) {
        int used = 0;
#pragma unroll
        for (int k = 0; k < 3; k++) {
            float bv = -FLT_MAX; int bi = 0x7fffffff; int bs = -1;
#pragma unroll
            for (int t = 0; t < 8; t++) {
                if (used & (1 << t)) continue;
                if (better(c_val[t], c_idx[t], bv, bi)) { bv = c_val[t]; bi = c_idx[t]; bs = t; }
            }
            used |= (1 << bs);
            sel_s[k] = bi; hit_s[k] = (bv >= 0.0f);
        }
        g_anyhit[row] = hit_s[0] | hit_s[1] | hit_s[2];
        g_hit3[row * 3 + 0] = hit_s[0];
        g_hit3[row * 3 + 1] = hit_s[1];
        g_hit3[row * 3 + 2] = hit_s[2];
    }
    __syncthreads();

#pragma unroll
    for (int t = 0; t < 3; t++) {
        int idx = sel_s[t];
        for (int d = tid; d < VDIM; d += 128)
            g_retr[((size_t)row * 3 + t) * VDIM + d] = values[(size_t)idx * VDIM + d];
    }
}

// ---------------- K6M: attention + softmax + mem_vec -> g_comb (4 rows/CTA, unroll-8) ----------------
#define K6M_SMEM ((12 * 256 + 12 * 132) * 4)   // 18624 B
__global__ void __launch_bounds__(256) k6m(const float* __restrict__ S,
                                           const float* __restrict__ aw1,
                                           const float* __restrict__ aw2,
                                           const float* __restrict__ ab2) {
    extern __shared__ char dsm[];
    float* retr = (float*)dsm;          // [12][256]
    float* red  = retr + 12 * 256;      // [12][132]
    __shared__ float sterm_s[4 * 128];
    __shared__ float lgs[12];
    __shared__ float attn_s[4][3];

    const int row0 = blockIdx.x * 4;
    const int tid = threadIdx.x;

    for (int idx = tid; idx < 12 * VDIM; idx += 256)
        retr[idx] = g_retr[(size_t)row0 * 3 * VDIM + idx];
    for (int idx = tid; idx < 4 * AH; idx += 256)
        sterm_s[idx] = g_sterm[(size_t)row0 * AH + idx];
    __syncthreads();

    {
        int j = tid & 127, grp = tid >> 7;  // grp handles 6 triples
        float acc[6];
#pragma unroll
        for (int rt = 0; rt < 6; rt++) acc[rt] = sterm_s[((grp * 6 + rt) / 3) * 128 + j];
        for (int k = 0; k < VDIM; k += 8) {
            float w[8];
#pragma unroll
            for (int u = 0; u < 8; u++) w[u] = aw1[(EDIM + k + u) * AH + j];
#pragma unroll
            for (int u = 0; u < 8; u++) {
#pragma unroll
                for (int rt = 0; rt < 6; rt++) {
                    int g = grp * 6 + rt;
                    acc[rt] = fmaf(retr[g * 256 + k + u], w[u], acc[rt]);
                }
            }
        }
        float w2 = aw2[j];
#pragma unroll
        for (int rt = 0; rt < 6; rt++)
            red[(grp * 6 + rt) * 132 + j] = tanhf(acc[rt]) * w2;
    }
    __syncthreads();

    {
        int wid = tid >> 5, lane = tid & 31;
        float b2 = ab2[0];
#pragma unroll
        for (int u = 0; u < 2; u++) {
            int rt = wid * 2 + u;
            if (rt < 12) {
                float s = red[rt * 132 + lane] + red[rt * 132 + lane + 32]
                        + red[rt * 132 + lane + 64] + red[rt * 132 + lane + 96];
#pragma unroll
                for (int off = 16; off; off >>= 1) s += __shfl_xor_sync(0xffffffffu, s, off);
                if (lane == 0)
                    lgs[rt] = g_hit3[(size_t)row0 * 3 + rt] ? (s + b2) : NEG_BIG;
            }
        }
    }
    __syncthreads();
    if (tid < 4) {
        float l0 = lgs[tid * 3 + 0], l1 = lgs[tid * 3 + 1], l2 = lgs[tid * 3 + 2];
        float m = fmaxf(l0, fmaxf(l1, l2));
        float e0 = expf(l0 - m), e1 = expf(l1 - m), e2 = expf(l2 - m);
        float inv = 1.f / (e0 + e1 + e2);
        attn_s[tid][0] = e0 * inv; attn_s[tid][1] = e1 * inv; attn_s[tid][2] = e2 * inv;
    }
    __syncthreads();

    for (int idx = tid; idx < 4 * CDIM; idx += 256) {
        int r = idx >> 9, c = idx & 511;
        float val;
        if (c < EDIM) {
            val = S[(size_t)(row0 + r) * EDIM + c];
        } else {
            int d = c - EDIM;
            val = attn_s[r][0] * retr[(r * 3 + 0) * 256 + d]
                + attn_s[r][1] * retr[(r * 3 + 1) * 256 + d]
                + attn_s[r][2] * retr[(r * 3 + 2) * 256 + d];
        }
        g_comb[(size_t)(row0 + r) * CDIM + c] = val;
    }
}

// ---------------- K78: fused integration MLP (8 rows/CTA, g1 in smem) ----------------
__global__ void __launch_bounds__(256) k78(const float* __restrict__ W1, const float* __restrict__ b1,
                                           const float* __restrict__ W2, const float* __restrict__ b2,
                                           float* __restrict__ out) {
    __shared__ float xs[CDIM * 10];   // 20 KB, comb transposed
    __shared__ float sg[IH * 10];     // 20 KB, g1 transposed
    const int r0 = blockIdx.x * 8;
    const int tid = threadIdx.x;

    for (int i = tid; i < 8 * CDIM; i += 256) {
        int r = i >> 9, c = i & 511;
        xs[c * 10 + r] = g_comb[(size_t)(r0 + r) * CDIM + c];
    }
    __syncthreads();

    // phase 1: g1 = relu(comb @ W1 + b1) -> sg (each thread 2 output cols)
#pragma unroll 1
    for (int jj = 0; jj < 2; jj++) {
        int j = jj * 256 + tid;
        float bj = b1[j];
        ull acc[4];
#pragma unroll
        for (int p = 0; p < 4; p++) acc[p] = pack2(bj, bj);
        for (int k = 0; k < CDIM; k += 8) {
            float w[8];
#pragma unroll
            for (int u = 0; u < 8; u++) w[u] = W1[(k + u) * IH + j];
#pragma unroll
            for (int u = 0; u < 8; u++) {
                ull wp = pack2(w[u], w[u]);
#pragma unroll
                for (int p = 0; p < 4; p++)
                    fma2(acc[p], lds64(xs + (k + u) * 10 + 2 * p), wp);
            }
        }
#pragma unroll
        for (int p = 0; p < 4; p++) {
            float2 f = unpack2(acc[p]);
            sg[j * 10 + 2 * p]     = fmaxf(f.x, 0.f);
            sg[j * 10 + 2 * p + 1] = fmaxf(f.y, 0.f);
        }
    }
    __syncthreads();

    // phase 2: out = g1 @ W2 + b2
    {
        int j = tid;   // ODIM == 256
        float bj = b2[j];
        ull acc[4];
#pragma unroll
        for (int p = 0; p < 4; p++) acc[p] = pack2(bj, bj);
        for (int k = 0; k < IH; k += 8) {
            float w[8];
#pragma unroll
            for (int u = 0; u < 8; u++) w[u] = W2[(k + u) * ODIM + j];
#pragma unroll
            for (int u = 0; u < 8; u++) {
                ull wp = pack2(w[u], w[u]);
#pragma unroll
                for (int p = 0; p < 4; p++)
                    fma2(acc[p], lds64(sg + (k + u) * 10 + 2 * p), wp);
            }
        }
#pragma unroll
        for (int p = 0; p < 4; p++) {
            float2 f = unpack2(acc[p]);
            out[(size_t)(r0 + 2 * p) * ODIM + j]     = f.x;
            out[(size_t)(r0 + 2 * p + 1) * ODIM + j] = f.y;
        }
    }
}

// ---------------- K9: fallback path for rows with no hit (rare/never) ----------------
__global__ void k9_fallback(const float* __restrict__ S,
                            const float* __restrict__ fw1, const float* __restrict__ fb1,
                            const float* __restrict__ fw2, const float* __restrict__ fb2,
                            float* __restrict__ out) {
    int row = blockIdx.x;
    if (g_anyhit[row]) return;
    __shared__ float xs[EDIM];
    __shared__ float h[IH];
    int tid = threadIdx.x;  // 256
    for (int i = tid; i < EDIM; i += 256) xs[i] = S[(size_t)row * EDIM + i];
    __syncthreads();
    for (int j = tid; j < IH; j += 256) {
        float a = fb1[j];
        for (int k = 0; k < EDIM; k++) a = fmaf(xs[k], fw1[k * IH + j], a);
        h[j] = fmaxf(a, 0.f);
    }
    __syncthreads();
    {
        int j = tid;
        float a = fb2[j];
        for (int k = 0; k < IH; k++) a = fmaf(h[k], fw2[k * ODIM + j], a);
        out[(size_t)row * ODIM + j] = a;
    }
}

// ---------------- launch ----------------
extern "C" void kernel_launch(void* const* d_in, const int* in_sizes, int n_in,
                              void* d_out, int out_size) {
    const float* S    = (const float*)d_in[0];
    const float* keys = (const float*)d_in[1];
    const float* vals = (const float*)d_in[2];
    const float* kw1  = (const float*)d_in[3];
    const float* kb1  = (const float*)d_in[4];
    const float* kw2  = (const float*)d_in[5];
    const float* kb2  = (const float*)d_in[6];
    const float* aw1  = (const float*)d_in[7];
    const float* ab1  = (const float*)d_in[8];
    const float* aw2  = (const float*)d_in[9];
    const float* ab2  = (const float*)d_in[10];
    const float* iw1  = (const float*)d_in[11];
    const float* ib1  = (const float*)d_in[12];
    const float* iw2  = (const float*)d_in[13];
    const float* ib2  = (const float*)d_in[14];
    const float* fw1  = (const float*)d_in[15];
    const float* fb1  = (const float*)d_in[16];
    const float* fw2  = (const float*)d_in[17];
    const float* fb2  = (const float*)d_in[18];
    float* out = (float*)d_out;

    static int configured = 0;
    if (!configured) {
        cudaFuncSetAttribute(k4_gemm, cudaFuncAttributeMaxDynamicSharedMemorySize, SMEM_K4);
        configured = 1;
    }

    kc_keys<<<MKEYS / 8, 256>>>(keys);
    k12<<<BQ / 4, 256>>>(S, kw1, kb1, kw2, kb2, aw1, ab1);
    k4_gemm<<<dim3(GX, BQ / 128), 256, SMEM_K4>>>();
    k5sel<<<BQ, 128>>>(keys, vals);
    k6m<<<BQ / 4, 256, K6M_SMEM>>>(S, aw1, aw2, ab2);
    k78<<<BQ / 8, 256>>>(iw1, ib1, iw2, ib2, out);
    k9_fallback<<<BQ, 256>>>(S, fw1, fb1, fw2, fb2, out);
}

// round 15
// speedup vs baseline: 1.0859x; 1.0115x over previous
#include <cuda_runtime.h>
#include <cuda_bf16.h>
#include <math.h>
#include <float.h>
#include <stdint.h>

#define BQ     2048
#define MKEYS  131072
#define EDIM   256
#define KDIM   128
#define VDIM   256
#define ODIM   256
#define H1     512
#define AH     128
#define IH     512
#define CDIM   (EDIM + VDIM)   // 512
#define GX     128             // CTAs along key dim in k4
#define NT     8               // key tiles (128 keys) per CTA
#define NCAND  (GX * 2 * 2)    // 512 candidates per row (top-2 per (bx, wn))
#define NEG_BIG (-1e9f)

// ---------------- scratch (static device globals; no allocation) ----------------
__device__ float g_qn[BQ * KDIM];                           // 1 MB
__device__ __align__(16) __nv_bfloat16 g_qhi[BQ * KDIM];    // 512 KB
__device__ __align__(16) __nv_bfloat16 g_khi[MKEYS * KDIM]; // 32 MB
__device__ float g_invn[MKEYS];                             // 0.5 MB
__device__ float g_p3val[BQ * NCAND];                       // 4.2 MB (idx reconstructed from payload)
__device__ float g_sterm[BQ * AH];                          // 1 MB
__device__ int   g_topidx[BQ * 3];
__device__ int   g_hit3[BQ * 3];
__device__ int   g_anyhit[BQ];
__device__ float g_comb[BQ * CDIM];                         // 4 MB

// ================= helpers =================
typedef unsigned long long ull;
__device__ __forceinline__ ull pack2(float x, float y) {
    ull r; asm("mov.b64 %0, {%1, %2};" : "=l"(r) : "f"(x), "f"(y)); return r;
}
__device__ __forceinline__ void fma2(ull& d, ull a, ull b) {
    asm("fma.rn.f32x2 %0, %1, %2, %0;" : "+l"(d) : "l"(a), "l"(b));
}
__device__ __forceinline__ float2 unpack2(ull v) {
    float2 f; asm("mov.b64 {%0, %1}, %2;" : "=f"(f.x), "=f"(f.y) : "l"(v)); return f;
}
__device__ __forceinline__ ull lds64(const float* p) { return *(const ull*)p; }
__device__ __forceinline__ uint32_t smem_u32(const void* p) {
    uint32_t a;
    asm("{ .reg .u64 t; cvta.to.shared.u64 t, %1; cvt.u32.u64 %0, t; }" : "=r"(a) : "l"(p));
    return a;
}
__device__ __forceinline__ void ldsm4(uint32_t* r, uint32_t addr) {
    asm volatile("ldmatrix.sync.aligned.m8n8.x4.shared.b16 {%0,%1,%2,%3}, [%4];"
                 : "=r"(r[0]), "=r"(r[1]), "=r"(r[2]), "=r"(r[3]) : "r"(addr));
}
__device__ __forceinline__ void mma16816(float* d, const uint32_t* a, const uint32_t* b) {
    asm volatile(
        "mma.sync.aligned.m16n8k16.row.col.f32.bf16.bf16.f32 "
        "{%0,%1,%2,%3}, {%4,%5,%6,%7}, {%8,%9}, {%0,%1,%2,%3};"
        : "+f"(d[0]), "+f"(d[1]), "+f"(d[2]), "+f"(d[3])
        : "r"(a[0]), "r"(a[1]), "r"(a[2]), "r"(a[3]), "r"(b[0]), "r"(b[1]));
}
__device__ __forceinline__ void cp16(uint32_t saddr, const void* gaddr) {
    asm volatile("cp.async.cg.shared.global [%0], [%1], 16;" :: "r"(saddr), "l"(gaddr));
}
#define CP_COMMIT() asm volatile("cp.async.commit_group;" ::: "memory")
#define CP_WAIT0()  asm volatile("cp.async.wait_group 0;" ::: "memory")

__device__ __forceinline__ void ins2(float& v0, float& v1, float p) {
    float t = fminf(v0, p);
    v0 = fmaxf(v0, p);
    v1 = fmaxf(v1, t);
}
__device__ __forceinline__ bool better(float v, int i, float V, int I) {
    return (v > V) || (v == V && (unsigned)i < (unsigned)I);
}

// ---------------- KC: key inverse norms + normalized bf16 keys ----------------
__global__ void kc_keys(const float* __restrict__ keys) {
    int row = blockIdx.x * 8 + (threadIdx.x >> 5);
    int lane = threadIdx.x & 31;
    float4 v = ((const float4*)keys)[(size_t)row * 32 + lane];
    float s = v.x * v.x + v.y * v.y + v.z * v.z + v.w * v.w;
#pragma unroll
    for (int o = 16; o > 0; o >>= 1) s += __shfl_xor_sync(0xffffffffu, s, o);
    float in = 1.f / fmaxf(sqrtf(s), 1e-8f);
    if (lane == 0) g_invn[row] = in;
    unsigned short hb[4];
    hb[0] = __bfloat16_as_ushort(__float2bfloat16(v.x * in));
    hb[1] = __bfloat16_as_ushort(__float2bfloat16(v.y * in));
    hb[2] = __bfloat16_as_ushort(__float2bfloat16(v.z * in));
    hb[3] = __bfloat16_as_ushort(__float2bfloat16(v.w * in));
    uint2 uh;
    uh.x = (uint32_t)hb[0] | ((uint32_t)hb[1] << 16);
    uh.y = (uint32_t)hb[2] | ((uint32_t)hb[3] << 16);
    ((uint2*)g_khi)[(size_t)row * 32 + lane] = uh;
}

// ---------------- K12: fused key-encoder MLP + normalize + sterm (4 rows/CTA) ----------------
__global__ void __launch_bounds__(256) k12(const float* __restrict__ S,
                                           const float* __restrict__ kw1, const float* __restrict__ kb1,
                                           const float* __restrict__ kw2, const float* __restrict__ kb2,
                                           const float* __restrict__ aw1, const float* __restrict__ ab1) {
    __shared__ float sx[EDIM * 6];        // S transposed [c][r], 6 KB
    __shared__ float sh[H1 * 6];          // hidden transposed, 12 KB
    __shared__ float part[2][4][128];     // split-K partials, 4 KB
    __shared__ float qs[4][128];
    __shared__ float sinv[4];
    const int r0 = blockIdx.x * 4;
    const int tid = threadIdx.x;
    const int j128 = tid & 127, half = tid >> 7;

    for (int i = tid; i < 4 * EDIM; i += 256) {
        int r = i >> 8, c = i & 255;
        sx[c * 6 + r] = S[(size_t)(r0 + r) * EDIM + c];
    }
    __syncthreads();

    // phase 1: hidden = relu(S @ kw1 + kb1) -> sh (each thread 2 output cols)
#pragma unroll 1
    for (int jj = 0; jj < 2; jj++) {
        int j = jj * 256 + tid;
        float bj = kb1[j];
        ull acc[2];
        acc[0] = pack2(bj, bj); acc[1] = acc[0];
        for (int k = 0; k < EDIM; k += 8) {
            float w[8];
#pragma unroll
            for (int u = 0; u < 8; u++) w[u] = kw1[(k + u) * H1 + j];
#pragma unroll
            for (int u = 0; u < 8; u++) {
                ull wp = pack2(w[u], w[u]);
                fma2(acc[0], lds64(sx + (k + u) * 6 + 0), wp);
                fma2(acc[1], lds64(sx + (k + u) * 6 + 2), wp);
            }
        }
#pragma unroll
        for (int p = 0; p < 2; p++) {
            float2 f = unpack2(acc[p]);
            sh[j * 6 + 2 * p]     = fmaxf(f.x, 0.f);
            sh[j * 6 + 2 * p + 1] = fmaxf(f.y, 0.f);
        }
    }

    // phase S: sterm partials = S @ aw1_top (split-K over 256)
    {
        ull acc[2] = { 0ull, 0ull };
        int kbeg = half * 128;
        for (int k = kbeg; k < kbeg + 128; k += 8) {
            float w[8];
#pragma unroll
            for (int u = 0; u < 8; u++) w[u] = aw1[(k + u) * AH + j128];
#pragma unroll
            for (int u = 0; u < 8; u++) {
                ull wp = pack2(w[u], w[u]);
                fma2(acc[0], lds64(sx + (k + u) * 6 + 0), wp);
                fma2(acc[1], lds64(sx + (k + u) * 6 + 2), wp);
            }
        }
#pragma unroll
        for (int p = 0; p < 2; p++) {
            float2 f = unpack2(acc[p]);
            part[half][2 * p][j128]     = f.x;
            part[half][2 * p + 1][j128] = f.y;
        }
    }
    __syncthreads();
    if (tid < 128) {
        float bj = ab1[tid];
#pragma unroll
        for (int r = 0; r < 4; r++)
            g_sterm[(size_t)(r0 + r) * AH + tid] = part[0][r][tid] + part[1][r][tid] + bj;
    }
    __syncthreads();

    // phase 2: query = hidden @ kw2 (split-K over 512)
    {
        ull acc[2] = { 0ull, 0ull };
        int kbeg = half * 256;
        for (int k = kbeg; k < kbeg + 256; k += 8) {
            float w[8];
#pragma unroll
            for (int u = 0; u < 8; u++) w[u] = kw2[(k + u) * KDIM + j128];
#pragma unroll
            for (int u = 0; u < 8; u++) {
                ull wp = pack2(w[u], w[u]);
                fma2(acc[0], lds64(sh + (k + u) * 6 + 0), wp);
                fma2(acc[1], lds64(sh + (k + u) * 6 + 2), wp);
            }
        }
#pragma unroll
        for (int p = 0; p < 2; p++) {
            float2 f = unpack2(acc[p]);
            part[half][2 * p][j128]     = f.x;
            part[half][2 * p + 1][j128] = f.y;
        }
    }
    __syncthreads();
    if (tid < 128) {
        float bj = kb2[tid];
#pragma unroll
        for (int r = 0; r < 4; r++)
            qs[r][tid] = part[0][r][tid] + part[1][r][tid] + bj;
    }
    __syncthreads();
    {
        int wid = tid >> 5, lane = tid & 31;
        if (wid < 4) {
            float a0 = qs[wid][lane],      a1 = qs[wid][lane + 32];
            float a2 = qs[wid][lane + 64], a3 = qs[wid][lane + 96];
            float s = a0 * a0 + a1 * a1 + a2 * a2 + a3 * a3;
#pragma unroll
            for (int off = 16; off; off >>= 1) s += __shfl_xor_sync(0xffffffffu, s, off);
            if (lane == 0) sinv[wid] = 1.f / fmaxf(sqrtf(s), 1e-8f);
        }
    }
    __syncthreads();
    for (int i = tid; i < 4 * KDIM; i += 256) {
        int r = i >> 7, c = i & 127;
        float x = qs[r][c] * sinv[r];
        g_qn[(size_t)(r0 + r) * KDIM + c] = x;
        g_qhi[(size_t)(r0 + r) * KDIM + c] = __float2bfloat16(x);
    }
}

// ---------------- K4: bf16 HMMA GEMM + running per-lane top-2 (val-only output) ----------------
#define AROW   136
#define TILEB  (128 * AROW * 2)     // 34816
#define SMEM_K4 (3 * TILEB)         // 104448

__device__ __forceinline__ void load_tile_cp(uint32_t sdst, const __nv_bfloat16* __restrict__ g,
                                             int grow0, int tid) {
#pragma unroll
    for (int i = 0; i < 8; i++) {
        int idx = i * 256 + tid;
        int r = idx >> 4, c = idx & 15;
        cp16(sdst + r * (AROW * 2) + c * 16, (const void*)(g + (size_t)(grow0 + r) * KDIM + c * 8));
    }
}

__global__ void __launch_bounds__(256, 2) k4_gemm() {
    extern __shared__ char smem[];
    const uint32_t sb = smem_u32(smem);
    const uint32_t sA = sb, sB0 = sb + TILEB, sB1 = sb + 2 * TILEB;
    const int tid = threadIdx.x;
    const int lane = tid & 31, w = tid >> 5;
    const int wm = w & 3, wn = w >> 2;       // warp grid 4M x 2N
    const int row0 = blockIdx.y * 128;
    const int bx = blockIdx.x;
    const int m0 = wm * 32;

    uint32_t aAddr[2];
#pragma unroll
    for (int f = 0; f < 2; f++)
        aAddr[f] = sA + (uint32_t)(((m0 + f * 16 + (lane & 15)) * AROW + ((lane >> 4) & 1) * 8) * 2);
    const uint32_t bLane = (uint32_t)(((((lane & 7) + ((lane >> 4) << 3)) * AROW) + ((lane >> 3) & 1) * 8) * 2);

    load_tile_cp(sA, g_qhi, row0, tid);
    load_tile_cp(sB0, g_khi, bx * 128, tid);
    CP_COMMIT();
    CP_WAIT0();
    __syncthreads();

    float tv0[4], tv1[4];
#pragma unroll
    for (int r = 0; r < 4; r++) { tv0[r] = -FLT_MAX; tv1[r] = -FLT_MAX; }
    const unsigned qb1 = (unsigned)((lane & 3) << 1);

    for (int i = 0; i < NT; i++) {
        const uint32_t sBuf = (i & 1) ? sB1 : sB0;
        if (i + 1 < NT) {
            load_tile_cp((i & 1) ? sB0 : sB1, g_khi, ((i + 1) * GX + bx) * 128, tid);
        }
        CP_COMMIT();

        float acc[2][8][4];
#pragma unroll
        for (int f = 0; f < 2; f++)
#pragma unroll
            for (int j8 = 0; j8 < 8; j8++)
#pragma unroll
                for (int q = 0; q < 4; q++) acc[f][j8][q] = 0.f;

#pragma unroll
        for (int s = 0; s < 8; s++) {
            uint32_t a0[4], a1[4];
            ldsm4(a0, aAddr[0] + s * 32);
            ldsm4(a1, aAddr[1] + s * 32);
#pragma unroll
            for (int g = 0; g < 4; g++) {
                uint32_t bf[4];
                ldsm4(bf, sBuf + bLane + (uint32_t)(((wn * 4 + g) * 16) * (AROW * 2)) + s * 32);
                mma16816(acc[0][2 * g],     a0, bf);
                mma16816(acc[0][2 * g + 1], a0, bf + 2);
                mma16816(acc[1][2 * g],     a1, bf);
                mma16816(acc[1][2 * g + 1], a1, bf + 2);
            }
        }

        // running top-2: pack 9-bit payload (tile i: 3b, col-in-64: 6b) into mantissa
        const unsigned ibase = (unsigned)(i << 6) | qb1;
#pragma unroll
        for (int f = 0; f < 2; f++)
#pragma unroll
            for (int j8 = 0; j8 < 8; j8++)
#pragma unroll
                for (int q = 0; q < 4; q++) {
                    int ridx = f * 2 + (q >> 1);
                    unsigned pay = ibase | ((unsigned)j8 << 3) | (unsigned)(q & 1);
                    float p = __uint_as_float((__float_as_uint(acc[f][j8][q]) & 0xFFFFFE00u) | pay);
                    ins2(tv0[ridx], tv1[ridx], p);
                }

        CP_WAIT0();
        __syncthreads();
    }

    // merge across quad
#pragma unroll
    for (int off = 1; off <= 2; off <<= 1) {
#pragma unroll
        for (int r = 0; r < 4; r++) {
            float u0 = __shfl_xor_sync(0xffffffffu, tv0[r], off);
            float u1 = __shfl_xor_sync(0xffffffffu, tv1[r], off);
            ins2(tv0[r], tv1[r], u0);
            ins2(tv0[r], tv1[r], u1);
        }
    }
    if ((lane & 3) == 0) {
        const int r_lo = lane >> 2;
#pragma unroll
        for (int r = 0; r < 4; r++) {
            int grow = row0 + m0 + (r >> 1) * 16 + r_lo + (r & 1) * 8;
            size_t base = (((size_t)grow * GX + bx) * 2 + wn) * 2;
            g_p3val[base + 0] = tv0[r];
            g_p3val[base + 1] = tv1[r];
        }
    }
}

// ---------------- K5SEL: warp-local top-8 (idx reconstructed) -> rescore -> top-3 ----------------
__global__ void __launch_bounds__(128) k5sel(const float* __restrict__ keys) {
    int row = blockIdx.x;
    int tid = threadIdx.x;  // 128
    int lane = tid & 31, w = tid >> 5;
    __shared__ float qrow[KDIM];
    __shared__ float wcval[4][8];
    __shared__ int   wcid[4][8];
    __shared__ int   c_idx[8];
    __shared__ float c_val[8];

    qrow[tid] = g_qn[(size_t)row * KDIM + tid];

    // warp w owns candidates [w*128, w*128+128); idx reconstructed from position + payload
    float v[4]; int id[4];
#pragma unroll
    for (int t = 0; t < 4; t++) {
        int e = w * 128 + t * 32 + lane;
        float val = g_p3val[(size_t)row * NCAND + e];
        v[t] = val;
        unsigned pay = __float_as_uint(val) & 511u;
        int bx = e >> 2, wnn = (e >> 1) & 1;
        id[t] = ((int)(pay >> 6) * GX + bx) * 128 + wnn * 64 + (int)(pay & 63u);
    }
    // warp-local top-8 (8 shfl-argmax rounds, no block syncs)
#pragma unroll 1
    for (int r = 0; r < 8; r++) {
        float lv = v[0]; int lt = 0;
#pragma unroll
        for (int t = 1; t < 4; t++) if (v[t] > lv) { lv = v[t]; lt = t; }
        int lid = id[lt];
        int lpos = lt * 32 + lane;
#pragma unroll
        for (int off = 16; off; off >>= 1) {
            float ov = __shfl_xor_sync(0xffffffffu, lv, off);
            int   oi = __shfl_xor_sync(0xffffffffu, lid, off);
            int   op = __shfl_xor_sync(0xffffffffu, lpos, off);
            if (ov > lv || (ov == lv && op < lpos)) { lv = ov; lid = oi; lpos = op; }
        }
        if ((lpos & 31) == lane) v[lpos >> 5] = -FLT_MAX;   // winner lane invalidates
        if (lane == 0) { wcval[w][r] = lv; wcid[w][r] = lid; }
    }
    __syncthreads();

    // warp 0 merges 4x8 -> global top-8
    if (w == 0) {
        float mv = wcval[lane >> 3][lane & 7];
        int   mi = wcid[lane >> 3][lane & 7];
#pragma unroll 1
        for (int r = 0; r < 8; r++) {
            float bv = mv; int bi = mi; int bp = lane;
#pragma unroll
            for (int off = 16; off; off >>= 1) {
                float ov = __shfl_xor_sync(0xffffffffu, bv, off);
                int   oi = __shfl_xor_sync(0xffffffffu, bi, off);
                int   op = __shfl_xor_sync(0xffffffffu, bp, off);
                if (ov > bv || (ov == bv && op < bp)) { bv = ov; bi = oi; bp = op; }
            }
            if (lane == bp) mv = -FLT_MAX;
            if (lane == 0) c_idx[r] = bi;
        }
    }
    __syncthreads();

    // exact fp32 rescore of 8 candidates
    {
        int c = tid >> 4, l = tid & 15;
        int idx = c_idx[c];
        float part = 0.f;
#pragma unroll
        for (int jj = 0; jj < 8; jj++) {
            int k = l + jj * 16;
            part += qrow[k] * keys[(size_t)idx * KDIM + k];
        }
#pragma unroll
        for (int off = 8; off; off >>= 1) part += __shfl_xor_sync(0xffffffffu, part, off);
        if (l == 0) c_val[c] = part * g_invn[idx];
    }
    __syncthreads();

    if (tid == 0) {
        int used = 0;
        int anyh = 0;
#pragma unroll
        for (int k = 0; k < 3; k++) {
            float bv = -FLT_MAX; int bi = 0x7fffffff; int bs = -1;
#pragma unroll
            for (int t = 0; t < 8; t++) {
                if (used & (1 << t)) continue;
                if (better(c_val[t], c_idx[t], bv, bi)) { bv = c_val[t]; bi = c_idx[t]; bs = t; }
            }
            used |= (1 << bs);
            int h = (bv >= 0.0f);
            g_topidx[row * 3 + k] = bi;
            g_hit3[row * 3 + k] = h;
            anyh |= h;
        }
        g_anyhit[row] = anyh;
    }
}

// ---------------- K6M: gather + attention + softmax + mem_vec -> g_comb (4 rows/CTA) ----------------
#define K6M_SMEM ((12 * 256 + 12 * 132) * 4)   // 18624 B
__global__ void __launch_bounds__(256) k6m(const float* __restrict__ S,
                                           const float* __restrict__ values,
                                           const float* __restrict__ aw1,
                                           const float* __restrict__ aw2,
                                           const float* __restrict__ ab2) {
    extern __shared__ char dsm[];
    float* retr = (float*)dsm;          // [12][256]
    float* red  = retr + 12 * 256;      // [12][132]
    __shared__ float sterm_s[4 * 128];
    __shared__ float lgs[12];
    __shared__ float attn_s[4][3];
    __shared__ int   sidx[12];

    const int row0 = blockIdx.x * 4;
    const int tid = threadIdx.x;

    if (tid < 12) sidx[tid] = g_topidx[(size_t)row0 * 3 + tid];
    for (int idx = tid; idx < 4 * AH; idx += 256)
        sterm_s[idx] = g_sterm[(size_t)row0 * AH + idx];
    __syncthreads();

    // gather retrieved value rows directly from values
    for (int idx = tid; idx < 12 * VDIM; idx += 256) {
        int t = idx >> 8, d = idx & 255;
        retr[idx] = values[(size_t)sidx[t] * VDIM + d];
    }
    __syncthreads();

    {
        int j = tid & 127, grp = tid >> 7;  // grp handles 6 triples
        float acc[6];
#pragma unroll
        for (int rt = 0; rt < 6; rt++) acc[rt] = sterm_s[((grp * 6 + rt) / 3) * 128 + j];
        for (int k = 0; k < VDIM; k += 8) {
            float w[8];
#pragma unroll
            for (int u = 0; u < 8; u++) w[u] = aw1[(EDIM + k + u) * AH + j];
#pragma unroll
            for (int u = 0; u < 8; u++) {
#pragma unroll
                for (int rt = 0; rt < 6; rt++) {
                    int g = grp * 6 + rt;
                    acc[rt] = fmaf(retr[g * 256 + k + u], w[u], acc[rt]);
                }
            }
        }
        float w2 = aw2[j];
#pragma unroll
        for (int rt = 0; rt < 6; rt++)
            red[(grp * 6 + rt) * 132 + j] = tanhf(acc[rt]) * w2;
    }
    __syncthreads();

    {
        int wid = tid >> 5, lane = tid & 31;
        float b2 = ab2[0];
#pragma unroll
        for (int u = 0; u < 2; u++) {
            int rt = wid * 2 + u;
            if (rt < 12) {
                float s = red[rt * 132 + lane] + red[rt * 132 + lane + 32]
                        + red[rt * 132 + lane + 64] + red[rt * 132 + lane + 96];
#pragma unroll
                for (int off = 16; off; off >>= 1) s += __shfl_xor_sync(0xffffffffu, s, off);
                if (lane == 0)
                    lgs[rt] = g_hit3[(size_t)row0 * 3 + rt] ? (s + b2) : NEG_BIG;
            }
        }
    }
    __syncthreads();
    if (tid < 4) {
        float l0 = lgs[tid * 3 + 0], l1 = lgs[tid * 3 + 1], l2 = lgs[tid * 3 + 2];
        float m = fmaxf(l0, fmaxf(l1, l2));
        float e0 = expf(l0 - m), e1 = expf(l1 - m), e2 = expf(l2 - m);
        float inv = 1.f / (e0 + e1 + e2);
        attn_s[tid][0] = e0 * inv; attn_s[tid][1] = e1 * inv; attn_s[tid][2] = e2 * inv;
    }
    __syncthreads();

    for (int idx = tid; idx < 4 * CDIM; idx += 256) {
        int r = idx >> 9, c = idx & 511;
        float val;
        if (c < EDIM) {
            val = S[(size_t)(row0 + r) * EDIM + c];
        } else {
            int d = c - EDIM;
            val = attn_s[r][0] * retr[(r * 3 + 0) * 256 + d]
                + attn_s[r][1] * retr[(r * 3 + 1) * 256 + d]
                + attn_s[r][2] * retr[(r * 3 + 2) * 256 + d];
        }
        g_comb[(size_t)(row0 + r) * CDIM + c] = val;
    }
}

// ---------------- K78: fused integration MLP (8 rows/CTA, g1 in smem) ----------------
__global__ void __launch_bounds__(256) k78(const float* __restrict__ W1, const float* __restrict__ b1,
                                           const float* __restrict__ W2, const float* __restrict__ b2,
                                           float* __restrict__ out) {
    __shared__ float xs[CDIM * 10];   // 20 KB, comb transposed
    __shared__ float sg[IH * 10];     // 20 KB, g1 transposed
    const int r0 = blockIdx.x * 8;
    const int tid = threadIdx.x;

    for (int i = tid; i < 8 * CDIM; i += 256) {
        int r = i >> 9, c = i & 511;
        xs[c * 10 + r] = g_comb[(size_t)(r0 + r) * CDIM + c];
    }
    __syncthreads();

    // phase 1: g1 = relu(comb @ W1 + b1) -> sg (each thread 2 output cols)
#pragma unroll 1
    for (int jj = 0; jj < 2; jj++) {
        int j = jj * 256 + tid;
        float bj = b1[j];
        ull acc[4];
#pragma unroll
        for (int p = 0; p < 4; p++) acc[p] = pack2(bj, bj);
        for (int k = 0; k < CDIM; k += 8) {
            float w[8];
#pragma unroll
            for (int u = 0; u < 8; u++) w[u] = W1[(k + u) * IH + j];
#pragma unroll
            for (int u = 0; u < 8; u++) {
                ull wp = pack2(w[u], w[u]);
#pragma unroll
                for (int p = 0; p < 4; p++)
                    fma2(acc[p], lds64(xs + (k + u) * 10 + 2 * p), wp);
            }
        }
#pragma unroll
        for (int p = 0; p < 4; p++) {
            float2 f = unpack2(acc[p]);
            sg[j * 10 + 2 * p]     = fmaxf(f.x, 0.f);
            sg[j * 10 + 2 * p + 1] = fmaxf(f.y, 0.f);
        }
    }
    __syncthreads();

    // phase 2: out = g1 @ W2 + b2
    {
        int j = tid;   // ODIM == 256
        float bj = b2[j];
        ull acc[4];
#pragma unroll
        for (int p = 0; p < 4; p++) acc[p] = pack2(bj, bj);
        for (int k = 0; k < IH; k += 8) {
            float w[8];
#pragma unroll
            for (int u = 0; u < 8; u++) w[u] = W2[(k + u) * ODIM + j];
#pragma unroll
            for (int u = 0; u < 8; u++) {
                ull wp = pack2(w[u], w[u]);
#pragma unroll
                for (int p = 0; p < 4; p++)
                    fma2(acc[p], lds64(sg + (k + u) * 10 + 2 * p), wp);
            }
        }
#pragma unroll
        for (int p = 0; p < 4; p++) {
            float2 f = unpack2(acc[p]);
            out[(size_t)(r0 + 2 * p) * ODIM + j]     = f.x;
            out[(size_t)(r0 + 2 * p + 1) * ODIM + j] = f.y;
        }
    }
}

// ---------------- K9: fallback path for rows with no hit (rare/never) ----------------
__global__ void k9_fallback(const float* __restrict__ S,
                            const float* __restrict__ fw1, const float* __restrict__ fb1,
                            const float* __restrict__ fw2, const float* __restrict__ fb2,
                            float* __restrict__ out) {
    int row = blockIdx.x;
    if (g_anyhit[row]) return;
    __shared__ float xs[EDIM];
    __shared__ float h[IH];
    int tid = threadIdx.x;  // 256
    for (int i = tid; i < EDIM; i += 256) xs[i] = S[(size_t)row * EDIM + i];
    __syncthreads();
    for (int j = tid; j < IH; j += 256) {
        float a = fb1[j];
        for (int k = 0; k < EDIM; k++) a = fmaf(xs[k], fw1[k * IH + j], a);
        h[j] = fmaxf(a, 0.f);
    }
    __syncthreads();
    {
        int j = tid;
        float a = fb2[j];
        for (int k = 0; k < IH; k++) a = fmaf(h[k], fw2[k * ODIM + j], a);
        out[(size_t)row * ODIM + j] = a;
    }
}

// ---------------- launch ----------------
extern "C" void kernel_launch(void* const* d_in, const int* in_sizes, int n_in,
                              void* d_out, int out_size) {
    const float* S    = (const float*)d_in[0];
    const float* keys = (const float*)d_in[1];
    const float* vals = (const float*)d_in[2];
    const float* kw1  = (const float*)d_in[3];
    const float* kb1  = (const float*)d_in[4];
    const float* kw2  = (const float*)d_in[5];
    const float* kb2  = (const float*)d_in[6];
    const float* aw1  = (const float*)d_in[7];
    const float* ab1  = (const float*)d_in[8];
    const float* aw2  = (const float*)d_in[9];
    const float* ab2  = (const float*)d_in[10];
    const float* iw1  = (const float*)d_in[11];
    const float* ib1  = (const float*)d_in[12];
    const float* iw2  = (const float*)d_in[13];
    const float* ib2  = (const float*)d_in[14];
    const float* fw1  = (const float*)d_in[15];
    const float* fb1  = (const float*)d_in[16];
    const float* fw2  = (const float*)d_in[17];
    const float* fb2  = (const float*)d_in[18];
    float* out = (float*)d_out;

    static int configured = 0;
    static cudaStream_t s2;
    static cudaEvent_t evF, evJ;
    if (!configured) {
        cudaFuncSetAttribute(k4_gemm, cudaFuncAttributeMaxDynamicSharedMemorySize, SMEM_K4);
        cudaStreamCreateWithFlags(&s2, cudaStreamNonBlocking);
        cudaEventCreateWithFlags(&evF, cudaEventDisableTiming);
        cudaEventCreateWithFlags(&evJ, cudaEventDisableTiming);
        configured = 1;
    }

    // fork: kc_keys runs on s2 concurrently with k12 on the main stream
    cudaEventRecord(evF, 0);
    cudaStreamWaitEvent(s2, evF, 0);
    kc_keys<<<MKEYS / 8, 256, 0, s2>>>(keys);
    cudaEventRecord(evJ, s2);
    k12<<<BQ / 4, 256>>>(S, kw1, kb1, kw2, kb2, aw1, ab1);
    cudaStreamWaitEvent(0, evJ, 0);   // join before k4

    k4_gemm<<<dim3(GX, BQ / 128), 256, SMEM_K4>>>();
    k5sel<<<BQ, 128>>>(keys);
    k6m<<<BQ / 4, 256, K6M_SMEM>>>(S, vals, aw1, aw2, ab2);
    k78<<<BQ / 8, 256>>>(iw1, ib1, iw2, ib2, out);
    k9_fallback<<<BQ, 256>>>(S, fw1, fb1, fw2, fb2, out);
}

// round 16
// speedup vs baseline: 1.1243x; 1.0354x over previous
#include <cuda_runtime.h>
#include <cuda_bf16.h>
#include <math.h>
#include <float.h>
#include <stdint.h>

#define BQ     2048
#define MKEYS  131072
#define EDIM   256
#define KDIM   128
#define VDIM   256
#define ODIM   256
#define H1     512
#define AH     128
#define IH     512
#define CDIM   (EDIM + VDIM)   // 512
#define GX     128             // CTAs along key dim in k4
#define NT     8               // key tiles (128 keys) per CTA
#define NCAND  (GX * 2 * 2)    // 512 candidates per row (top-2 per (bx, wn))
#define NEG_BIG (-1e9f)
#define HALF_ROWS (BQ / 2)     // 1024

// ---------------- scratch (static device globals; no allocation) ----------------
__device__ float g_qn[BQ * KDIM];                           // 1 MB
__device__ __align__(16) __nv_bfloat16 g_qhi[BQ * KDIM];    // 512 KB
__device__ __align__(16) __nv_bfloat16 g_khi[MKEYS * KDIM]; // 32 MB
__device__ float g_invn[MKEYS];                             // 0.5 MB
__device__ float g_p3val[BQ * NCAND];                       // 4.2 MB (idx reconstructed from payload)
__device__ float g_sterm[BQ * AH];                          // 1 MB
__device__ int   g_topidx[BQ * 3];
__device__ int   g_hit3[BQ * 3];
__device__ int   g_anyhit[BQ];
__device__ float g_comb[BQ * CDIM];                         // 4 MB

// ================= helpers =================
typedef unsigned long long ull;
__device__ __forceinline__ ull pack2(float x, float y) {
    ull r; asm("mov.b64 %0, {%1, %2};" : "=l"(r) : "f"(x), "f"(y)); return r;
}
__device__ __forceinline__ void fma2(ull& d, ull a, ull b) {
    asm("fma.rn.f32x2 %0, %1, %2, %0;" : "+l"(d) : "l"(a), "l"(b));
}
__device__ __forceinline__ float2 unpack2(ull v) {
    float2 f; asm("mov.b64 {%0, %1}, %2;" : "=f"(f.x), "=f"(f.y) : "l"(v)); return f;
}
__device__ __forceinline__ ull lds64(const float* p) { return *(const ull*)p; }
__device__ __forceinline__ uint32_t smem_u32(const void* p) {
    uint32_t a;
    asm("{ .reg .u64 t; cvta.to.shared.u64 t, %1; cvt.u32.u64 %0, t; }" : "=r"(a) : "l"(p));
    return a;
}
__device__ __forceinline__ void ldsm4(uint32_t* r, uint32_t addr) {
    asm volatile("ldmatrix.sync.aligned.m8n8.x4.shared.b16 {%0,%1,%2,%3}, [%4];"
                 : "=r"(r[0]), "=r"(r[1]), "=r"(r[2]), "=r"(r[3]) : "r"(addr));
}
__device__ __forceinline__ void mma16816(float* d, const uint32_t* a, const uint32_t* b) {
    asm volatile(
        "mma.sync.aligned.m16n8k16.row.col.f32.bf16.bf16.f32 "
        "{%0,%1,%2,%3}, {%4,%5,%6,%7}, {%8,%9}, {%0,%1,%2,%3};"
        : "+f"(d[0]), "+f"(d[1]), "+f"(d[2]), "+f"(d[3])
        : "r"(a[0]), "r"(a[1]), "r"(a[2]), "r"(a[3]), "r"(b[0]), "r"(b[1]));
}
__device__ __forceinline__ void cp16(uint32_t saddr, const void* gaddr) {
    asm volatile("cp.async.cg.shared.global [%0], [%1], 16;" :: "r"(saddr), "l"(gaddr));
}
#define CP_COMMIT() asm volatile("cp.async.commit_group;" ::: "memory")
#define CP_WAIT0()  asm volatile("cp.async.wait_group 0;" ::: "memory")

__device__ __forceinline__ void ins2(float& v0, float& v1, float p) {
    float t = fminf(v0, p);
    v0 = fmaxf(v0, p);
    v1 = fmaxf(v1, t);
}
__device__ __forceinline__ bool better(float v, int i, float V, int I) {
    return (v > V) || (v == V && (unsigned)i < (unsigned)I);
}

// ---------------- KC: key inverse norms + normalized bf16 keys ----------------
__global__ void kc_keys(const float* __restrict__ keys) {
    int row = blockIdx.x * 8 + (threadIdx.x >> 5);
    int lane = threadIdx.x & 31;
    float4 v = ((const float4*)keys)[(size_t)row * 32 + lane];
    float s = v.x * v.x + v.y * v.y + v.z * v.z + v.w * v.w;
#pragma unroll
    for (int o = 16; o > 0; o >>= 1) s += __shfl_xor_sync(0xffffffffu, s, o);
    float in = 1.f / fmaxf(sqrtf(s), 1e-8f);
    if (lane == 0) g_invn[row] = in;
    unsigned short hb[4];
    hb[0] = __bfloat16_as_ushort(__float2bfloat16(v.x * in));
    hb[1] = __bfloat16_as_ushort(__float2bfloat16(v.y * in));
    hb[2] = __bfloat16_as_ushort(__float2bfloat16(v.z * in));
    hb[3] = __bfloat16_as_ushort(__float2bfloat16(v.w * in));
    uint2 uh;
    uh.x = (uint32_t)hb[0] | ((uint32_t)hb[1] << 16);
    uh.y = (uint32_t)hb[2] | ((uint32_t)hb[3] << 16);
    ((uint2*)g_khi)[(size_t)row * 32 + lane] = uh;
}

// ---------------- K12: fused key-encoder MLP + normalize + sterm (4 rows/CTA) ----------------
__global__ void __launch_bounds__(256) k12(const float* __restrict__ S,
                                           const float* __restrict__ kw1, const float* __restrict__ kb1,
                                           const float* __restrict__ kw2, const float* __restrict__ kb2,
                                           const float* __restrict__ aw1, const float* __restrict__ ab1) {
    __shared__ float sx[EDIM * 6];
    __shared__ float sh[H1 * 6];
    __shared__ float part[2][4][128];
    __shared__ float qs[4][128];
    __shared__ float sinv[4];
    const int r0 = blockIdx.x * 4;
    const int tid = threadIdx.x;
    const int j128 = tid & 127, half = tid >> 7;

    for (int i = tid; i < 4 * EDIM; i += 256) {
        int r = i >> 8, c = i & 255;
        sx[c * 6 + r] = S[(size_t)(r0 + r) * EDIM + c];
    }
    __syncthreads();

#pragma unroll 1
    for (int jj = 0; jj < 2; jj++) {
        int j = jj * 256 + tid;
        float bj = kb1[j];
        ull acc[2];
        acc[0] = pack2(bj, bj); acc[1] = acc[0];
        for (int k = 0; k < EDIM; k += 8) {
            float w[8];
#pragma unroll
            for (int u = 0; u < 8; u++) w[u] = kw1[(k + u) * H1 + j];
#pragma unroll
            for (int u = 0; u < 8; u++) {
                ull wp = pack2(w[u], w[u]);
                fma2(acc[0], lds64(sx + (k + u) * 6 + 0), wp);
                fma2(acc[1], lds64(sx + (k + u) * 6 + 2), wp);
            }
        }
#pragma unroll
        for (int p = 0; p < 2; p++) {
            float2 f = unpack2(acc[p]);
            sh[j * 6 + 2 * p]     = fmaxf(f.x, 0.f);
            sh[j * 6 + 2 * p + 1] = fmaxf(f.y, 0.f);
        }
    }

    {
        ull acc[2] = { 0ull, 0ull };
        int kbeg = half * 128;
        for (int k = kbeg; k < kbeg + 128; k += 8) {
            float w[8];
#pragma unroll
            for (int u = 0; u < 8; u++) w[u] = aw1[(k + u) * AH + j128];
#pragma unroll
            for (int u = 0; u < 8; u++) {
                ull wp = pack2(w[u], w[u]);
                fma2(acc[0], lds64(sx + (k + u) * 6 + 0), wp);
                fma2(acc[1], lds64(sx + (k + u) * 6 + 2), wp);
            }
        }
#pragma unroll
        for (int p = 0; p < 2; p++) {
            float2 f = unpack2(acc[p]);
            part[half][2 * p][j128]     = f.x;
            part[half][2 * p + 1][j128] = f.y;
        }
    }
    __syncthreads();
    if (tid < 128) {
        float bj = ab1[tid];
#pragma unroll
        for (int r = 0; r < 4; r++)
            g_sterm[(size_t)(r0 + r) * AH + tid] = part[0][r][tid] + part[1][r][tid] + bj;
    }
    __syncthreads();

    {
        ull acc[2] = { 0ull, 0ull };
        int kbeg = half * 256;
        for (int k = kbeg; k < kbeg + 256; k += 8) {
            float w[8];
#pragma unroll
            for (int u = 0; u < 8; u++) w[u] = kw2[(k + u) * KDIM + j128];
#pragma unroll
            for (int u = 0; u < 8; u++) {
                ull wp = pack2(w[u], w[u]);
                fma2(acc[0], lds64(sh + (k + u) * 6 + 0), wp);
                fma2(acc[1], lds64(sh + (k + u) * 6 + 2), wp);
            }
        }
#pragma unroll
        for (int p = 0; p < 2; p++) {
            float2 f = unpack2(acc[p]);
            part[half][2 * p][j128]     = f.x;
            part[half][2 * p + 1][j128] = f.y;
        }
    }
    __syncthreads();
    if (tid < 128) {
        float bj = kb2[tid];
#pragma unroll
        for (int r = 0; r < 4; r++)
            qs[r][tid] = part[0][r][tid] + part[1][r][tid] + bj;
    }
    __syncthreads();
    {
        int wid = tid >> 5, lane = tid & 31;
        if (wid < 4) {
            float a0 = qs[wid][lane],      a1 = qs[wid][lane + 32];
            float a2 = qs[wid][lane + 64], a3 = qs[wid][lane + 96];
            float s = a0 * a0 + a1 * a1 + a2 * a2 + a3 * a3;
#pragma unroll
            for (int off = 16; off; off >>= 1) s += __shfl_xor_sync(0xffffffffu, s, off);
            if (lane == 0) sinv[wid] = 1.f / fmaxf(sqrtf(s), 1e-8f);
        }
    }
    __syncthreads();
    for (int i = tid; i < 4 * KDIM; i += 256) {
        int r = i >> 7, c = i & 127;
        float x = qs[r][c] * sinv[r];
        g_qn[(size_t)(r0 + r) * KDIM + c] = x;
        g_qhi[(size_t)(r0 + r) * KDIM + c] = __float2bfloat16(x);
    }
}

// ---------------- K4: bf16 HMMA GEMM + running per-lane top-2 (row-half variant) ----------------
#define AROW   136
#define TILEB  (128 * AROW * 2)     // 34816
#define SMEM_K4 (3 * TILEB)         // 104448

__device__ __forceinline__ void load_tile_cp(uint32_t sdst, const __nv_bfloat16* __restrict__ g,
                                             int grow0, int tid) {
#pragma unroll
    for (int i = 0; i < 8; i++) {
        int idx = i * 256 + tid;
        int r = idx >> 4, c = idx & 15;
        cp16(sdst + r * (AROW * 2) + c * 16, (const void*)(g + (size_t)(grow0 + r) * KDIM + c * 8));
    }
}

__global__ void __launch_bounds__(256, 2) k4_gemm(int rowBase) {
    extern __shared__ char smem[];
    const uint32_t sb = smem_u32(smem);
    const uint32_t sA = sb, sB0 = sb + TILEB, sB1 = sb + 2 * TILEB;
    const int tid = threadIdx.x;
    const int lane = tid & 31, w = tid >> 5;
    const int wm = w & 3, wn = w >> 2;       // warp grid 4M x 2N
    const int row0 = rowBase + blockIdx.y * 128;
    const int bx = blockIdx.x;
    const int m0 = wm * 32;

    uint32_t aAddr[2];
#pragma unroll
    for (int f = 0; f < 2; f++)
        aAddr[f] = sA + (uint32_t)(((m0 + f * 16 + (lane & 15)) * AROW + ((lane >> 4) & 1) * 8) * 2);
    const uint32_t bLane = (uint32_t)(((((lane & 7) + ((lane >> 4) << 3)) * AROW) + ((lane >> 3) & 1) * 8) * 2);

    load_tile_cp(sA, g_qhi, row0, tid);
    load_tile_cp(sB0, g_khi, bx * 128, tid);
    CP_COMMIT();
    CP_WAIT0();
    __syncthreads();

    float tv0[4], tv1[4];
#pragma unroll
    for (int r = 0; r < 4; r++) { tv0[r] = -FLT_MAX; tv1[r] = -FLT_MAX; }
    const unsigned qb1 = (unsigned)((lane & 3) << 1);

    for (int i = 0; i < NT; i++) {
        const uint32_t sBuf = (i & 1) ? sB1 : sB0;
        if (i + 1 < NT) {
            load_tile_cp((i & 1) ? sB0 : sB1, g_khi, ((i + 1) * GX + bx) * 128, tid);
        }
        CP_COMMIT();

        float acc[2][8][4];
#pragma unroll
        for (int f = 0; f < 2; f++)
#pragma unroll
            for (int j8 = 0; j8 < 8; j8++)
#pragma unroll
                for (int q = 0; q < 4; q++) acc[f][j8][q] = 0.f;

#pragma unroll
        for (int s = 0; s < 8; s++) {
            uint32_t a0[4], a1[4];
            ldsm4(a0, aAddr[0] + s * 32);
            ldsm4(a1, aAddr[1] + s * 32);
#pragma unroll
            for (int g = 0; g < 4; g++) {
                uint32_t bf[4];
                ldsm4(bf, sBuf + bLane + (uint32_t)(((wn * 4 + g) * 16) * (AROW * 2)) + s * 32);
                mma16816(acc[0][2 * g],     a0, bf);
                mma16816(acc[0][2 * g + 1], a0, bf + 2);
                mma16816(acc[1][2 * g],     a1, bf);
                mma16816(acc[1][2 * g + 1], a1, bf + 2);
            }
        }

        const unsigned ibase = (unsigned)(i << 6) | qb1;
#pragma unroll
        for (int f = 0; f < 2; f++)
#pragma unroll
            for (int j8 = 0; j8 < 8; j8++)
#pragma unroll
                for (int q = 0; q < 4; q++) {
                    int ridx = f * 2 + (q >> 1);
                    unsigned pay = ibase | ((unsigned)j8 << 3) | (unsigned)(q & 1);
                    float p = __uint_as_float((__float_as_uint(acc[f][j8][q]) & 0xFFFFFE00u) | pay);
                    ins2(tv0[ridx], tv1[ridx], p);
                }

        CP_WAIT0();
        __syncthreads();
    }

#pragma unroll
    for (int off = 1; off <= 2; off <<= 1) {
#pragma unroll
        for (int r = 0; r < 4; r++) {
            float u0 = __shfl_xor_sync(0xffffffffu, tv0[r], off);
            float u1 = __shfl_xor_sync(0xffffffffu, tv1[r], off);
            ins2(tv0[r], tv1[r], u0);
            ins2(tv0[r], tv1[r], u1);
        }
    }
    if ((lane & 3) == 0) {
        const int r_lo = lane >> 2;
#pragma unroll
        for (int r = 0; r < 4; r++) {
            int grow = row0 + m0 + (r >> 1) * 16 + r_lo + (r & 1) * 8;
            size_t base = (((size_t)grow * GX + bx) * 2 + wn) * 2;
            g_p3val[base + 0] = tv0[r];
            g_p3val[base + 1] = tv1[r];
        }
    }
}

// ---------------- K5SEL: warp-local top-8 -> rescore -> top-3 (row-half variant) ----------------
__global__ void __launch_bounds__(128) k5sel(const float* __restrict__ keys, int rowBase) {
    int row = rowBase + blockIdx.x;
    int tid = threadIdx.x;  // 128
    int lane = tid & 31, w = tid >> 5;
    __shared__ float qrow[KDIM];
    __shared__ float wcval[4][8];
    __shared__ int   wcid[4][8];
    __shared__ int   c_idx[8];
    __shared__ float c_val[8];

    qrow[tid] = g_qn[(size_t)row * KDIM + tid];

    float v[4]; int id[4];
#pragma unroll
    for (int t = 0; t < 4; t++) {
        int e = w * 128 + t * 32 + lane;
        float val = g_p3val[(size_t)row * NCAND + e];
        v[t] = val;
        unsigned pay = __float_as_uint(val) & 511u;
        int bx = e >> 2, wnn = (e >> 1) & 1;
        id[t] = ((int)(pay >> 6) * GX + bx) * 128 + wnn * 64 + (int)(pay & 63u);
    }
#pragma unroll 1
    for (int r = 0; r < 8; r++) {
        float lv = v[0]; int lt = 0;
#pragma unroll
        for (int t = 1; t < 4; t++) if (v[t] > lv) { lv = v[t]; lt = t; }
        int lid = id[lt];
        int lpos = lt * 32 + lane;
#pragma unroll
        for (int off = 16; off; off >>= 1) {
            float ov = __shfl_xor_sync(0xffffffffu, lv, off);
            int   oi = __shfl_xor_sync(0xffffffffu, lid, off);
            int   op = __shfl_xor_sync(0xffffffffu, lpos, off);
            if (ov > lv || (ov == lv && op < lpos)) { lv = ov; lid = oi; lpos = op; }
        }
        if ((lpos & 31) == lane) v[lpos >> 5] = -FLT_MAX;
        if (lane == 0) { wcval[w][r] = lv; wcid[w][r] = lid; }
    }
    __syncthreads();

    if (w == 0) {
        float mv = wcval[lane >> 3][lane & 7];
        int   mi = wcid[lane >> 3][lane & 7];
#pragma unroll 1
        for (int r = 0; r < 8; r++) {
            float bv = mv; int bi = mi; int bp = lane;
#pragma unroll
            for (int off = 16; off; off >>= 1) {
                float ov = __shfl_xor_sync(0xffffffffu, bv, off);
                int   oi = __shfl_xor_sync(0xffffffffu, bi, off);
                int   op = __shfl_xor_sync(0xffffffffu, bp, off);
                if (ov > bv || (ov == bv && op < bp)) { bv = ov; bi = oi; bp = op; }
            }
            if (lane == bp) mv = -FLT_MAX;
            if (lane == 0) c_idx[r] = bi;
        }
    }
    __syncthreads();

    {
        int c = tid >> 4, l = tid & 15;
        int idx = c_idx[c];
        float part = 0.f;
#pragma unroll
        for (int jj = 0; jj < 8; jj++) {
            int k = l + jj * 16;
            part += qrow[k] * keys[(size_t)idx * KDIM + k];
        }
#pragma unroll
        for (int off = 8; off; off >>= 1) part += __shfl_xor_sync(0xffffffffu, part, off);
        if (l == 0) c_val[c] = part * g_invn[idx];
    }
    __syncthreads();

    if (tid == 0) {
        int used = 0;
        int anyh = 0;
#pragma unroll
        for (int k = 0; k < 3; k++) {
            float bv = -FLT_MAX; int bi = 0x7fffffff; int bs = -1;
#pragma unroll
            for (int t = 0; t < 8; t++) {
                if (used & (1 << t)) continue;
                if (better(c_val[t], c_idx[t], bv, bi)) { bv = c_val[t]; bi = c_idx[t]; bs = t; }
            }
            used |= (1 << bs);
            int h = (bv >= 0.0f);
            g_topidx[row * 3 + k] = bi;
            g_hit3[row * 3 + k] = h;
            anyh |= h;
        }
        g_anyhit[row] = anyh;
    }
}

// ---------------- K6M: gather + attention + softmax + mem_vec -> g_comb (row-half) ----------------
#define K6M_SMEM ((12 * 256 + 12 * 132) * 4)   // 18624 B
__global__ void __launch_bounds__(256) k6m(const float* __restrict__ S,
                                           const float* __restrict__ values,
                                           const float* __restrict__ aw1,
                                           const float* __restrict__ aw2,
                                           const float* __restrict__ ab2, int rowBase) {
    extern __shared__ char dsm[];
    float* retr = (float*)dsm;          // [12][256]
    float* red  = retr + 12 * 256;      // [12][132]
    __shared__ float sterm_s[4 * 128];
    __shared__ float lgs[12];
    __shared__ float attn_s[4][3];
    __shared__ int   sidx[12];

    const int row0 = rowBase + blockIdx.x * 4;
    const int tid = threadIdx.x;

    if (tid < 12) sidx[tid] = g_topidx[(size_t)row0 * 3 + tid];
    for (int idx = tid; idx < 4 * AH; idx += 256)
        sterm_s[idx] = g_sterm[(size_t)row0 * AH + idx];
    __syncthreads();

    for (int idx = tid; idx < 12 * VDIM; idx += 256) {
        int t = idx >> 8, d = idx & 255;
        retr[idx] = values[(size_t)sidx[t] * VDIM + d];
    }
    __syncthreads();

    {
        int j = tid & 127, grp = tid >> 7;
        float acc[6];
#pragma unroll
        for (int rt = 0; rt < 6; rt++) acc[rt] = sterm_s[((grp * 6 + rt) / 3) * 128 + j];
        for (int k = 0; k < VDIM; k += 8) {
            float w[8];
#pragma unroll
            for (int u = 0; u < 8; u++) w[u] = aw1[(EDIM + k + u) * AH + j];
#pragma unroll
            for (int u = 0; u < 8; u++) {
#pragma unroll
                for (int rt = 0; rt < 6; rt++) {
                    int g = grp * 6 + rt;
                    acc[rt] = fmaf(retr[g * 256 + k + u], w[u], acc[rt]);
                }
            }
        }
        float w2 = aw2[j];
#pragma unroll
        for (int rt = 0; rt < 6; rt++)
            red[(grp * 6 + rt) * 132 + j] = tanhf(acc[rt]) * w2;
    }
    __syncthreads();

    {
        int wid = tid >> 5, lane = tid & 31;
        float b2 = ab2[0];
#pragma unroll
        for (int u = 0; u < 2; u++) {
            int rt = wid * 2 + u;
            if (rt < 12) {
                float s = red[rt * 132 + lane] + red[rt * 132 + lane + 32]
                        + red[rt * 132 + lane + 64] + red[rt * 132 + lane + 96];
#pragma unroll
                for (int off = 16; off; off >>= 1) s += __shfl_xor_sync(0xffffffffu, s, off);
                if (lane == 0)
                    lgs[rt] = g_hit3[(size_t)row0 * 3 + rt] ? (s + b2) : NEG_BIG;
            }
        }
    }
    __syncthreads();
    if (tid < 4) {
        float l0 = lgs[tid * 3 + 0], l1 = lgs[tid * 3 + 1], l2 = lgs[tid * 3 + 2];
        float m = fmaxf(l0, fmaxf(l1, l2));
        float e0 = expf(l0 - m), e1 = expf(l1 - m), e2 = expf(l2 - m);
        float inv = 1.f / (e0 + e1 + e2);
        attn_s[tid][0] = e0 * inv; attn_s[tid][1] = e1 * inv; attn_s[tid][2] = e2 * inv;
    }
    __syncthreads();

    for (int idx = tid; idx < 4 * CDIM; idx += 256) {
        int r = idx >> 9, c = idx & 511;
        float val;
        if (c < EDIM) {
            val = S[(size_t)(row0 + r) * EDIM + c];
        } else {
            int d = c - EDIM;
            val = attn_s[r][0] * retr[(r * 3 + 0) * 256 + d]
                + attn_s[r][1] * retr[(r * 3 + 1) * 256 + d]
                + attn_s[r][2] * retr[(r * 3 + 2) * 256 + d];
        }
        g_comb[(size_t)(row0 + r) * CDIM + c] = val;
    }
}

// ---------------- K78: fused integration MLP (row-half) ----------------
__global__ void __launch_bounds__(256) k78(const float* __restrict__ W1, const float* __restrict__ b1,
                                           const float* __restrict__ W2, const float* __restrict__ b2,
                                           float* __restrict__ out, int rowBase) {
    __shared__ float xs[CDIM * 10];   // 20 KB
    __shared__ float sg[IH * 10];     // 20 KB
    const int r0 = rowBase + blockIdx.x * 8;
    const int tid = threadIdx.x;

    for (int i = tid; i < 8 * CDIM; i += 256) {
        int r = i >> 9, c = i & 511;
        xs[c * 10 + r] = g_comb[(size_t)(r0 + r) * CDIM + c];
    }
    __syncthreads();

#pragma unroll 1
    for (int jj = 0; jj < 2; jj++) {
        int j = jj * 256 + tid;
        float bj = b1[j];
        ull acc[4];
#pragma unroll
        for (int p = 0; p < 4; p++) acc[p] = pack2(bj, bj);
        for (int k = 0; k < CDIM; k += 8) {
            float w[8];
#pragma unroll
            for (int u = 0; u < 8; u++) w[u] = W1[(k + u) * IH + j];
#pragma unroll
            for (int u = 0; u < 8; u++) {
                ull wp = pack2(w[u], w[u]);
#pragma unroll
                for (int p = 0; p < 4; p++)
                    fma2(acc[p], lds64(xs + (k + u) * 10 + 2 * p), wp);
            }
        }
#pragma unroll
        for (int p = 0; p < 4; p++) {
            float2 f = unpack2(acc[p]);
            sg[j * 10 + 2 * p]     = fmaxf(f.x, 0.f);
            sg[j * 10 + 2 * p + 1] = fmaxf(f.y, 0.f);
        }
    }
    __syncthreads();

    {
        int j = tid;
        float bj = b2[j];
        ull acc[4];
#pragma unroll
        for (int p = 0; p < 4; p++) acc[p] = pack2(bj, bj);
        for (int k = 0; k < IH; k += 8) {
            float w[8];
#pragma unroll
            for (int u = 0; u < 8; u++) w[u] = W2[(k + u) * ODIM + j];
#pragma unroll
            for (int u = 0; u < 8; u++) {
                ull wp = pack2(w[u], w[u]);
#pragma unroll
                for (int p = 0; p < 4; p++)
                    fma2(acc[p], lds64(sg + (k + u) * 10 + 2 * p), wp);
            }
        }
#pragma unroll
        for (int p = 0; p < 4; p++) {
            float2 f = unpack2(acc[p]);
            out[(size_t)(r0 + 2 * p) * ODIM + j]     = f.x;
            out[(size_t)(r0 + 2 * p + 1) * ODIM + j] = f.y;
        }
    }
}

// ---------------- K9: fallback path for rows with no hit (row-half) ----------------
__global__ void k9_fallback(const float* __restrict__ S,
                            const float* __restrict__ fw1, const float* __restrict__ fb1,
                            const float* __restrict__ fw2, const float* __restrict__ fb2,
                            float* __restrict__ out, int rowBase) {
    int row = rowBase + blockIdx.x;
    if (g_anyhit[row]) return;
    __shared__ float xs[EDIM];
    __shared__ float h[IH];
    int tid = threadIdx.x;  // 256
    for (int i = tid; i < EDIM; i += 256) xs[i] = S[(size_t)row * EDIM + i];
    __syncthreads();
    for (int j = tid; j < IH; j += 256) {
        float a = fb1[j];
        for (int k = 0; k < EDIM; k++) a = fmaf(xs[k], fw1[k * IH + j], a);
        h[j] = fmaxf(a, 0.f);
    }
    __syncthreads();
    {
        int j = tid;
        float a = fb2[j];
        for (int k = 0; k < IH; k++) a = fmaf(h[k], fw2[k * ODIM + j], a);
        out[(size_t)row * ODIM + j] = a;
    }
}

// ---------------- launch ----------------
extern "C" void kernel_launch(void* const* d_in, const int* in_sizes, int n_in,
                              void* d_out, int out_size) {
    const float* S    = (const float*)d_in[0];
    const float* keys = (const float*)d_in[1];
    const float* vals = (const float*)d_in[2];
    const float* kw1  = (const float*)d_in[3];
    const float* kb1  = (const float*)d_in[4];
    const float* kw2  = (const float*)d_in[5];
    const float* kb2  = (const float*)d_in[6];
    const float* aw1  = (const float*)d_in[7];
    const float* ab1  = (const float*)d_in[8];
    const float* aw2  = (const float*)d_in[9];
    const float* ab2  = (const float*)d_in[10];
    const float* iw1  = (const float*)d_in[11];
    const float* ib1  = (const float*)d_in[12];
    const float* iw2  = (const float*)d_in[13];
    const float* ib2  = (const float*)d_in[14];
    const float* fw1  = (const float*)d_in[15];
    const float* fb1  = (const float*)d_in[16];
    const float* fw2  = (const float*)d_in[17];
    const float* fb2  = (const float*)d_in[18];
    float* out = (float*)d_out;

    static int configured = 0;
    static cudaStream_t s2, s3;
    static cudaEvent_t evF, evJ, evH0, evT0;
    if (!configured) {
        cudaFuncSetAttribute(k4_gemm, cudaFuncAttributeMaxDynamicSharedMemorySize, SMEM_K4);
        cudaStreamCreateWithFlags(&s2, cudaStreamNonBlocking);
        cudaStreamCreateWithFlags(&s3, cudaStreamNonBlocking);
        cudaEventCreateWithFlags(&evF, cudaEventDisableTiming);
        cudaEventCreateWithFlags(&evJ, cudaEventDisableTiming);
        cudaEventCreateWithFlags(&evH0, cudaEventDisableTiming);
        cudaEventCreateWithFlags(&evT0, cudaEventDisableTiming);
        configured = 1;
    }

    // fork: kc_keys on s2 || k12 on main
    cudaEventRecord(evF, 0);
    cudaStreamWaitEvent(s2, evF, 0);
    kc_keys<<<MKEYS / 8, 256, 0, s2>>>(keys);
    cudaEventRecord(evJ, s2);
    k12<<<BQ / 4, 256>>>(S, kw1, kb1, kw2, kb2, aw1, ab1);
    cudaStreamWaitEvent(0, evJ, 0);   // join before k4

    // k4 half 0 (rows 0..1023), then fork its tail chain onto s3 while k4 half 1 runs
    k4_gemm<<<dim3(GX, HALF_ROWS / 128), 256, SMEM_K4>>>(0);
    cudaEventRecord(evH0, 0);
    cudaStreamWaitEvent(s3, evH0, 0);
    k5sel<<<HALF_ROWS, 128, 0, s3>>>(keys, 0);
    k6m<<<HALF_ROWS / 4, 256, K6M_SMEM, s3>>>(S, vals, aw1, aw2, ab2, 0);
    k78<<<HALF_ROWS / 8, 256, 0, s3>>>(iw1, ib1, iw2, ib2, out, 0);
    k9_fallback<<<HALF_ROWS, 256, 0, s3>>>(S, fw1, fb1, fw2, fb2, out, 0);
    cudaEventRecord(evT0, s3);

    // k4 half 1 (rows 1024..2047) on main, then its tail chain on main
    k4_gemm<<<dim3(GX, HALF_ROWS / 128), 256, SMEM_K4>>>(HALF_ROWS);
    k5sel<<<HALF_ROWS, 128>>>(keys, HALF_ROWS);
    k6m<<<HALF_ROWS / 4, 256, K6M_SMEM>>>(S, vals, aw1, aw2, ab2, HALF_ROWS);
    k78<<<HALF_ROWS / 8, 256>>>(iw1, ib1, iw2, ib2, out, HALF_ROWS);
    k9_fallback<<<HALF_ROWS, 256>>>(S, fw1, fb1, fw2, fb2, out, HALF_ROWS);

    cudaStreamWaitEvent(0, evT0, 0);  // join s3 before harness sees completion
}